// round 10
// baseline (speedup 1.0000x reference)
#include <cuda_runtime.h>
#include <cuda_bf16.h>
#include <cuda_fp16.h>
#include <cstdint>

// ============================================================================
// HyperGRUCell — round 10: fp16 2-product HMMA GEMM + phase-split Gram hyp_fused
//   split_act : fp32 -> fp16 hi/lo for [inp; prev_h]           (K-major)
//   split_wt  : fp32 W[k][n] -> fp16 Wt[n][k] (transpose, K-major)
//   gemm6     : C = Ahi@W^T + Alo@W^T   (fp32 accum, HMMA, 2 products) [unchanged]
//   hyp_fused : 2-pass Gram, phase-split loads, VPT=2/512thr, <=64 regs no-spill
// ============================================================================

#define MDIM 4096
#define NDIM 1024
#define KDIM 1024
#define GSZ  ((size_t)MDIM * NDIM)

__device__ float  g_C[6ull * MDIM * NDIM];
__device__ __half g_Ah[8192ull * 1024];
__device__ __half g_Al[8192ull * 1024];
__device__ __half g_Wh[6144ull * 1024];

// ----------------------------------------------------------------------------
// split kernels (unchanged from round 9)
// ----------------------------------------------------------------------------
__global__ void __launch_bounds__(256) split_act(const float* __restrict__ inp,
                                                 const float* __restrict__ prevh)
{
    const size_t i = ((size_t)blockIdx.x * 256 + threadIdx.x) * 4;
    const size_t half = (size_t)MDIM * KDIM;
    const float* src = (i < half) ? (inp + i) : (prevh + (i - half));
    float4 v = *reinterpret_cast<const float4*>(src);
    float x[4] = {v.x, v.y, v.z, v.w};
    uint32_t hp[2], lp[2];
#pragma unroll
    for (int j = 0; j < 2; j++) {
        __half h0 = __float2half_rn(x[2 * j]);
        __half h1 = __float2half_rn(x[2 * j + 1]);
        __half l0 = __float2half_rn(x[2 * j] - __half2float(h0));
        __half l1 = __float2half_rn(x[2 * j + 1] - __half2float(h1));
        hp[j] = (uint32_t)__half_as_ushort(h0) |
                ((uint32_t)__half_as_ushort(h1) << 16);
        lp[j] = (uint32_t)__half_as_ushort(l0) |
                ((uint32_t)__half_as_ushort(l1) << 16);
    }
    *reinterpret_cast<uint2*>(reinterpret_cast<char*>(g_Ah) + i * 2) = make_uint2(hp[0], hp[1]);
    *reinterpret_cast<uint2*>(reinterpret_cast<char*>(g_Al) + i * 2) = make_uint2(lp[0], lp[1]);
}

struct WPtrs { const float* w[6]; };

__global__ void __launch_bounds__(256) split_wt(WPtrs wp)
{
    __shared__ float t[32][33];
    const int g = blockIdx.z;
    const float* __restrict__ W = wp.w[g];
    const int tx = threadIdx.x & 31, ty = threadIdx.x >> 5;
    const int n0 = blockIdx.x * 32, k0 = blockIdx.y * 32;
#pragma unroll
    for (int j = 0; j < 4; j++)
        t[ty + j * 8][tx] = W[(size_t)(k0 + ty + j * 8) * NDIM + n0 + tx];
    __syncthreads();
#pragma unroll
    for (int j = 0; j < 4; j++) {
        const float v = t[tx][ty + j * 8];
        const size_t o = (size_t)(g * 1024 + n0 + ty + j * 8) * KDIM + k0 + tx;
        g_Wh[o] = __float2half_rn(v);
    }
}

// ----------------------------------------------------------------------------
// gemm6 (unchanged from round 9 — near legacy HMMA rate floor)
// ----------------------------------------------------------------------------
#define SSTRIDE 40
#define MAT_ELEMS (128 * SSTRIDE)
#define STAGE_ELEMS (3 * MAT_ELEMS)
#define NSTAGE 3
#define SMEM_BYTES (NSTAGE * STAGE_ELEMS * 2)

__device__ __forceinline__ void cp16(uint32_t dst, const void* src)
{
    asm volatile("cp.async.cg.shared.global [%0], [%1], 16;"
                 :: "r"(dst), "l"(src) : "memory");
}
#define CP_COMMIT() asm volatile("cp.async.commit_group;" ::: "memory")
#define CP_WAIT(n)  asm volatile("cp.async.wait_group %0;" :: "n"(n) : "memory")

__device__ __forceinline__ void ldsm4(uint32_t* d, uint32_t addr)
{
    asm volatile("ldmatrix.sync.aligned.m8n8.x4.shared.b16 {%0,%1,%2,%3}, [%4];"
                 : "=r"(d[0]), "=r"(d[1]), "=r"(d[2]), "=r"(d[3]) : "r"(addr));
}

__device__ __forceinline__ void mma16816(float* c, const uint32_t* a,
                                         const uint32_t* b)
{
    asm volatile(
        "mma.sync.aligned.m16n8k16.row.col.f32.f16.f16.f32 "
        "{%0,%1,%2,%3}, {%4,%5,%6,%7}, {%8,%9}, {%0,%1,%2,%3};"
        : "+f"(c[0]), "+f"(c[1]), "+f"(c[2]), "+f"(c[3])
        : "r"(a[0]), "r"(a[1]), "r"(a[2]), "r"(a[3]), "r"(b[0]), "r"(b[1]));
}

__global__ void __launch_bounds__(256, 2) gemm6()
{
    extern __shared__ __half smem[];
    uint32_t sb;
    asm("{ .reg .u64 t; cvta.to.shared.u64 t, %1; cvt.u32.u64 %0, t; }"
        : "=r"(sb) : "l"(smem));

    const int tid  = threadIdx.x;
    const int lane = tid & 31, wid = tid >> 5;
    const int wm = wid >> 2, wn = wid & 3;

    const int g  = blockIdx.z;
    const int bm = blockIdx.y * 128;
    const int bn = blockIdx.x * 128;
    const int arow = ((g & 1) << 12) + bm;
    const int wrow = (g << 10) + bn;

    const __half* gb[3] = {
        g_Ah + (size_t)arow * KDIM, g_Al + (size_t)arow * KDIM,
        g_Wh + (size_t)wrow * KDIM};

    int l_mat[6], l_row[6], l_ch[6];
#pragma unroll
    for (int i = 0; i < 6; i++) {
        const int idx = tid + i * 256;
        l_mat[i] = idx >> 9;
        const int wi = idx & 511;
        l_row[i] = wi >> 2;
        l_ch[i]  = wi & 3;
    }

#define LOAD_STAGE(kt, s)                                                      \
    do {                                                                       \
        const uint32_t sbase_ = sb + (uint32_t)(s) * (STAGE_ELEMS * 2);        \
        _Pragma("unroll")                                                      \
        for (int i = 0; i < 6; i++) {                                          \
            const uint32_t dst = sbase_ +                                      \
                (uint32_t)(l_mat[i] * MAT_ELEMS + l_row[i] * SSTRIDE +         \
                           l_ch[i] * 8) * 2;                                   \
            cp16(dst, gb[l_mat[i]] + (size_t)l_row[i] * KDIM +                 \
                      (kt) * 32 + l_ch[i] * 8);                                \
        }                                                                      \
    } while (0)

    float acc[4][4][4];
#pragma unroll
    for (int mt = 0; mt < 4; mt++)
#pragma unroll
        for (int nt = 0; nt < 4; nt++)
#pragma unroll
            for (int j = 0; j < 4; j++) acc[mt][nt][j] = 0.f;

    LOAD_STAGE(0, 0); CP_COMMIT();
    LOAD_STAGE(1, 1); CP_COMMIT();
    LOAD_STAGE(2, 2); CP_COMMIT();

    const int a_r = (lane & 7) + ((lane >> 3) & 1) * 8;
    const int a_c = (lane >> 4) * 8;
    const int b_r = (lane & 7) + (lane >> 4) * 8;
    const int b_c = ((lane >> 3) & 1) * 8;

    for (int kt = 0; kt < 32; kt++) {
        CP_WAIT(2);
        __syncthreads();

        const int slot = kt % 3;
        const uint32_t sbase = sb + (uint32_t)slot * (STAGE_ELEMS * 2);
#pragma unroll
        for (int ks = 0; ks < 2; ks++) {
            uint32_t a[4][4], bq[4][2];
#pragma unroll
            for (int p = 0; p < 2; p++) {
                uint32_t q[4];
                ldsm4(q, sbase + (uint32_t)(2 * MAT_ELEMS +
                        (wn * 32 + p * 16 + b_r) * SSTRIDE + ks * 16 + b_c) * 2);
                bq[2 * p][0] = q[0]; bq[2 * p][1] = q[1];
                bq[2 * p + 1][0] = q[2]; bq[2 * p + 1][1] = q[3];
            }
#pragma unroll
            for (int mt = 0; mt < 4; mt++)
                ldsm4(a[mt], sbase +
                      (uint32_t)((wm * 64 + mt * 16 + a_r) * SSTRIDE +
                                 ks * 16 + a_c) * 2);
#pragma unroll
            for (int mt = 0; mt < 4; mt++)
#pragma unroll
                for (int nt = 0; nt < 4; nt++)
                    mma16816(acc[mt][nt], a[mt], bq[nt]);
#pragma unroll
            for (int mt = 0; mt < 4; mt++)
                ldsm4(a[mt], sbase +
                      (uint32_t)(MAT_ELEMS +
                                 (wm * 64 + mt * 16 + a_r) * SSTRIDE +
                                 ks * 16 + a_c) * 2);
#pragma unroll
            for (int mt = 0; mt < 4; mt++)
#pragma unroll
                for (int nt = 0; nt < 4; nt++)
                    mma16816(acc[mt][nt], a[mt], bq[nt]);
        }

        __syncthreads();
        if (kt + 3 < 32) LOAD_STAGE(kt + 3, slot);
        CP_COMMIT();
    }
    CP_WAIT(0);

    float* Cb = g_C + (size_t)g * GSZ;
    const int mrow = bm + wm * 64 + (lane >> 2);
    const int ncol = bn + wn * 32 + (lane & 3) * 2;
#pragma unroll
    for (int mt = 0; mt < 4; mt++) {
#pragma unroll
        for (int nt = 0; nt < 4; nt++) {
            float* p0 = Cb + (size_t)(mrow + mt * 16) * NDIM + ncol + nt * 8;
            *reinterpret_cast<float2*>(p0) =
                make_float2(acc[mt][nt][0], acc[mt][nt][1]);
            *reinterpret_cast<float2*>(p0 + 8 * NDIM) =
                make_float2(acc[mt][nt][2], acc[mt][nt][3]);
        }
    }
#undef LOAD_STAGE
}

// ----------------------------------------------------------------------------
// hyp_fused — 2-pass Gram, phase-split loads, VPT=2 / 512 threads
// ----------------------------------------------------------------------------
#define RT 512
#define VPT 2
#define NWARP 16

__device__ __forceinline__ float artanh_c(float x)
{
    x = fminf(fmaxf(x, -1.f + 1e-5f), 1.f - 1e-5f);
    return 0.5f * __logf(__fdividef(1.f + x, 1.f - x));
}

__device__ __forceinline__ float tanh_pos(float v)   // v >= 0
{
    return 1.f - __fdividef(2.f, __expf(2.f * v) + 1.f);
}

__device__ __forceinline__ float sigmoid_f(float v)
{
    return __fdividef(1.f, 1.f + __expf(-v));
}

__device__ __forceinline__ void safe_norm(float v2, float& inv_n, float& n)
{
    const float vc = fmaxf(v2, 1e-15f);
    inv_n = rsqrtf(vc);
    n = vc * inv_n;
}

__device__ __forceinline__ float mv_factor(float g2, float inv_xn, float atx)
{
    float inv_gn, gn;
    safe_norm(g2, inv_gn, gn);
    return tanh_pos(gn * inv_xn * atx) * inv_gn;
}

__device__ __forceinline__ void madd_coef(float ab, float a2, float b2,
                                          float& cA, float& cB)
{
    const float inv = __fdividef(1.f, 1.f + 2.f * ab + a2 * b2);
    cA = (1.f + 2.f * ab + b2) * inv;
    cB = (1.f - a2) * inv;
}

template <int N>
__device__ __forceinline__ void blockReduceN(float* v, float* buf)
{
    const int lane = threadIdx.x & 31, wid = threadIdx.x >> 5;
#pragma unroll
    for (int o = 16; o; o >>= 1)
#pragma unroll
        for (int i = 0; i < N; i++)
            v[i] += __shfl_xor_sync(0xffffffffu, v[i], o);
    if (lane == 0)
#pragma unroll
        for (int i = 0; i < N; i++) buf[wid * N + i] = v[i];
    __syncthreads();
#pragma unroll
    for (int i = 0; i < N; i++) {
        float s = 0.f;
#pragma unroll
        for (int w = 0; w < NWARP; w++) s += buf[w * N + i];
        v[i] = s;
    }
}

__global__ void __launch_bounds__(512, 2) hyp_fused(
    const float* __restrict__ inp, const float* __restrict__ prevh,
    const float* __restrict__ bzp, const float* __restrict__ brp,
    const float* __restrict__ bhp, float* __restrict__ out)
{
    __shared__ float buf[NWARP * 19];
    const int tid = threadIdx.x;
    const size_t off = (size_t)blockIdx.x * NDIM;

    float s[19];
#pragma unroll
    for (int i = 0; i < 19; i++) s[i] = 0.f;

    // ---- pass 1, phase A: x, H, G0, G1, BZ ----
#pragma unroll
    for (int j = 0; j < VPT; j++) {
        const int c = j * RT + tid;
        const float xv = inp[off + c];
        const float h  = prevh[off + c];
        const float g0 = g_C[0 * GSZ + off + c];
        const float g1 = g_C[1 * GSZ + off + c];
        const float bz = bzp[c];
        s[0] = fmaf(xv, xv, s[0]);     // xx
        s[1] = fmaf(h, h, s[1]);       // hh
        s[2] = fmaf(g0, g0, s[2]);     // g00
        s[3] = fmaf(g1, g1, s[3]);     // g11
        s[4] = fmaf(g0, g1, s[4]);     // g01
        s[5] = fmaf(g0, bz, s[5]);     // g0z
        s[6] = fmaf(g1, bz, s[6]);     // g1z
        s[7] = fmaf(bz, bz, s[7]);     // zz
    }
    // ---- pass 1, phase B: G2, G3, BR ----
#pragma unroll
    for (int j = 0; j < VPT; j++) {
        const int c = j * RT + tid;
        const float g2 = g_C[2 * GSZ + off + c];
        const float g3 = g_C[3 * GSZ + off + c];
        const float br = brp[c];
        s[8]  = fmaf(g2, g2, s[8]);    // g22
        s[9]  = fmaf(g3, g3, s[9]);    // g33
        s[10] = fmaf(g2, g3, s[10]);   // g23
        s[11] = fmaf(g2, br, s[11]);   // g2r
        s[12] = fmaf(g3, br, s[12]);   // g3r
        s[13] = fmaf(br, br, s[13]);   // rrb
    }
    // ---- pass 1, phase C: G5, BH, G4, H ----
#pragma unroll
    for (int j = 0; j < VPT; j++) {
        const int c = j * RT + tid;
        const float g5 = g_C[5 * GSZ + off + c];
        const float bh = bhp[c];
        const float g4 = g_C[4 * GSZ + off + c];
        const float h  = prevh[off + c];
        s[14] = fmaf(g5, g5, s[14]);   // g55
        s[15] = fmaf(g5, bh, s[15]);   // g5h
        s[16] = fmaf(bh, bh, s[16]);   // bhbh
        s[17] = fmaf(g4, g4, s[17]);   // g44
        s[18] = fmaf(g4, h, s[18]);    // g4H
    }
    blockReduceN<19>(s, buf);
    const float xx = s[0], hh = s[1];
    const float g00 = s[2], g11 = s[3], g01 = s[4], g0z = s[5], g1z = s[6], zz = s[7];
    const float g22 = s[8], g33 = s[9], g23 = s[10], g2r = s[11], g3r = s[12], rrb = s[13];
    const float g55 = s[14], g5h = s[15], bhbh = s[16], g44 = s[17], g4H = s[18];

    // ---- pass-1 scalar algebra (identical to round 9) ----
    float inv_xn, xn, inv_hn, hn;
    safe_norm(xx, inv_xn, xn);
    safe_norm(hh, inv_hn, hn);
    const float atx = artanh_c(xn);
    const float ath = artanh_c(hn);

    const float t0 = mv_factor(g00, inv_xn, atx);
    const float t1 = mv_factor(g11, inv_hn, ath);
    const float t2 = mv_factor(g22, inv_xn, atx);
    const float t3 = mv_factor(g33, inv_hn, ath);
    const float t4 = mv_factor(g44, inv_xn, atx);
    const float t5 = mv_factor(g55, inv_hn, ath);

    float cA, cB;
    // z gate coefficients
    madd_coef(t1 * g1z, t1 * t1 * g11, zz, cA, cB);
    const float u1 = cA * t1, u2 = cB;
    madd_coef(t0 * (u1 * g01 + u2 * g0z), t0 * t0 * g00,
              u1 * u1 * g11 + 2.f * u1 * u2 * g1z + u2 * u2 * zz, cA, cB);
    const float w0 = cA * t0, w1 = cB * u1, w2 = cB * u2;
    float fz;
    {
        const float nz2 = w0 * w0 * g00 + w1 * w1 * g11 + w2 * w2 * zz +
                          2.f * (w0 * w1 * g01 + w0 * w2 * g0z + w1 * w2 * g1z);
        float inv_nz, nz;
        safe_norm(nz2, inv_nz, nz);
        fz = artanh_c(nz) * inv_nz;
    }
    // r gate coefficients
    madd_coef(t3 * g3r, t3 * t3 * g33, rrb, cA, cB);
    const float v1 = cA * t3, v2 = cB;
    madd_coef(t2 * (v1 * g23 + v2 * g2r), t2 * t2 * g22,
              v1 * v1 * g33 + 2.f * v1 * v2 * g3r + v2 * v2 * rrb, cA, cB);
    const float y0 = cA * t2, y1 = cB * v1, y2 = cB * v2;
    float fr;
    {
        const float nr2 = y0 * y0 * g22 + y1 * y1 * g33 + y2 * y2 * rrb +
                          2.f * (y0 * y1 * g23 + y0 * y2 * g2r + y1 * y2 * g3r);
        float inv_nr, nr;
        safe_norm(nr2, inv_nr, nr);
        fr = artanh_c(nr) * inv_nr;
    }
    // ahh coefficients
    madd_coef(t5 * g5h, t5 * t5 * g55, bhbh, cA, cB);
    const float d5 = cA * t5, db = cB;
    const float ahh2 = d5 * d5 * g55 + 2.f * d5 * db * g5h + db * db * bhbh;

    // ---- pass 2: reload vectors, compute z/r/q on the fly + 12 sums ----
    float z[VPT], q[VPT], s2[12];
#pragma unroll
    for (int i = 0; i < 12; i++) s2[i] = 0.f;
#pragma unroll
    for (int j = 0; j < VPT; j++) {
        const int c = j * RT + tid;
        const float g0 = g_C[0 * GSZ + off + c];
        const float g1 = g_C[1 * GSZ + off + c];
        z[j] = sigmoid_f(fz * (w0 * g0 + w1 * g1 + w2 * bzp[c]));
        const float g2 = g_C[2 * GSZ + off + c];
        const float g3 = g_C[3 * GSZ + off + c];
        const float rv = sigmoid_f(fr * (y0 * g2 + y1 * g3 + y2 * brp[c]));
        const float g5 = g_C[5 * GSZ + off + c];
        q[j] = rv * fmaf(d5, g5, db * bhp[c]);
        const float g4 = g_C[4 * GSZ + off + c];
        const float h  = prevh[off + c];
        const float zh = z[j] * h, zq = z[j] * q[j], zg = z[j] * g4;
        s2[0]  = fmaf(q[j], q[j], s2[0]);     // qq
        s2[1]  = fmaf(q[j], g4, s2[1]);       // qg4
        s2[2]  = fmaf(q[j], h, s2[2]);        // qh
        s2[3]  = fmaf(zh, zh, s2[3]);         // s11
        s2[4]  = fmaf(zh, zq, s2[4]);         // s12
        s2[5]  = fmaf(zh, zg, s2[5]);         // s13
        s2[6]  = fmaf(zq, zq, s2[6]);         // s22
        s2[7]  = fmaf(zq, zg, s2[7]);         // s23
        s2[8]  = fmaf(zg, zg, s2[8]);         // s33
        s2[9]  = fmaf(h, zh, s2[9]);          // hzh
        s2[10] = fmaf(h, zq, s2[10]);         // hzq
        s2[11] = fmaf(h, zg, s2[11]);         // hzg4
    }
    __syncthreads();          // buf reuse safety
    blockReduceN<12>(s2, buf);
    const float qq = s2[0], qg4 = s2[1], qh = s2[2];
    const float s11 = s2[3], s12 = s2[4], s13 = s2[5];
    const float s22 = s2[6], s23 = s2[7], s33 = s2[8];
    const float hzh = s2[9], hzq = s2[10], hzg4 = s2[11];

    // ---- pass-2 scalar algebra (identical to round 9) ----
    float inv_na, na, inv_nq, nq;
    safe_norm(ahh2, inv_na, na);
    safe_norm(qq, inv_nq, nq);
    const float tp = tanh_pos(nq * inv_na * artanh_c(na)) * inv_nq;

    madd_coef(tp * t4 * qg4, tp * tp * qq, t4 * t4 * g44, cA, cB);
    const float bq = cA * tp, b4 = cB * t4;

    const float temp2 = bq * bq * qq + 2.f * bq * b4 * qg4 + b4 * b4 * g44;
    madd_coef(-(bq * qh + b4 * g4H), hh, temp2, cA, cB);
    const float alpha = -cA, bq2 = cB * bq, b42 = cB * b4;

    const float mh2 = alpha * alpha * hh + bq2 * bq2 * qq + b42 * b42 * g44 +
                      2.f * (alpha * bq2 * qh + alpha * b42 * g4H + bq2 * b42 * qg4);
    const float ux2 = alpha * alpha * s11 + bq2 * bq2 * s22 + b42 * b42 * s33 +
                      2.f * (alpha * bq2 * s12 + alpha * b42 * s13 + bq2 * b42 * s23);
    float inv_nmh, nmh, inv_nux, nux;
    safe_norm(mh2, inv_nmh, nmh);
    safe_norm(ux2, inv_nux, nux);
    const float tz = tanh_pos(nux * inv_nmh * artanh_c(nmh)) * inv_nux;

    madd_coef(tz * (alpha * hzh + bq2 * hzq + b42 * hzg4), hh, tz * tz * ux2,
              cA, cB);
    const float k0 = cA;
    const float kz = cB * tz;
    const float ka = kz * alpha, kb = kz * bq2, kc = kz * b42;

    // ---- output (reload H, G4) ----
#pragma unroll
    for (int j = 0; j < VPT; j++) {
        const int c = j * RT + tid;
        const float h  = prevh[off + c];
        const float g4 = g_C[4 * GSZ + off + c];
        out[off + c] = k0 * h + z[j] * (ka * h + kb * q[j] + kc * g4);
    }
}

// ----------------------------------------------------------------------------
// launch
// ----------------------------------------------------------------------------
extern "C" void kernel_launch(void* const* d_in, const int* in_sizes, int n_in,
                              void* d_out, int out_size)
{
    const float* inp   = (const float*)d_in[0];
    const float* prevh = (const float*)d_in[1];
    WPtrs wp;
    wp.w[0] = (const float*)d_in[2];  // w_inp_z
    wp.w[1] = (const float*)d_in[3];  // w_hid_z
    wp.w[2] = (const float*)d_in[5];  // w_inp_r
    wp.w[3] = (const float*)d_in[6];  // w_hid_r
    wp.w[4] = (const float*)d_in[8];  // w_inp_h
    wp.w[5] = (const float*)d_in[9];  // w_hid_h
    const float* b_z = (const float*)d_in[4];
    const float* b_r = (const float*)d_in[7];
    const float* b_h = (const float*)d_in[10];
    float* out = (float*)d_out;

    cudaFuncSetAttribute(gemm6, cudaFuncAttributeMaxDynamicSharedMemorySize,
                         SMEM_BYTES);

    split_act<<<8192, 256>>>(inp, prevh);
    split_wt<<<dim3(32, 32, 6), 256>>>(wp);
    gemm6<<<dim3(8, 32, 6), 256, SMEM_BYTES>>>();
    hyp_fused<<<MDIM, 512>>>(inp, prevh, b_z, b_r, b_h, out);
}

// round 11
// speedup vs baseline: 1.7578x; 1.7578x over previous
#include <cuda_runtime.h>
#include <cuda_bf16.h>
#include <cuda_fp16.h>
#include <cstdint>

// ============================================================================
// HyperGRUCell — round 11: single-product fp16 HMMA GEMM + round-9 Gram hyp_fused
//   split_act : fp32 -> fp16 for [inp; prev_h]                 (K-major)
//   split_wt  : fp32 W[k][n] -> fp16 Wt[n][k] (transpose, K-major)
//   gemm6     : C = A@W^T   (fp32 accum, HMMA, 1 product)
//   hyp_fused : 2-pass Gram (round-9 proven: VPT=4/256thr/110regs, 72.4us)
// ============================================================================

#define MDIM 4096
#define NDIM 1024
#define KDIM 1024
#define GSZ  ((size_t)MDIM * NDIM)

__device__ float  g_C[6ull * MDIM * NDIM];
__device__ __half g_Ah[8192ull * 1024];
__device__ __half g_Wh[6144ull * 1024];

// ----------------------------------------------------------------------------
// split kernels
// ----------------------------------------------------------------------------
__global__ void __launch_bounds__(256) split_act(const float* __restrict__ inp,
                                                 const float* __restrict__ prevh)
{
    const size_t i = ((size_t)blockIdx.x * 256 + threadIdx.x) * 4;
    const size_t half = (size_t)MDIM * KDIM;
    const float* src = (i < half) ? (inp + i) : (prevh + (i - half));
    float4 v = *reinterpret_cast<const float4*>(src);
    float x[4] = {v.x, v.y, v.z, v.w};
    uint32_t hp[2];
#pragma unroll
    for (int j = 0; j < 2; j++) {
        __half h0 = __float2half_rn(x[2 * j]);
        __half h1 = __float2half_rn(x[2 * j + 1]);
        hp[j] = (uint32_t)__half_as_ushort(h0) |
                ((uint32_t)__half_as_ushort(h1) << 16);
    }
    *reinterpret_cast<uint2*>(reinterpret_cast<char*>(g_Ah) + i * 2) = make_uint2(hp[0], hp[1]);
}

struct WPtrs { const float* w[6]; };

__global__ void __launch_bounds__(256) split_wt(WPtrs wp)
{
    __shared__ float t[32][33];
    const int g = blockIdx.z;
    const float* __restrict__ W = wp.w[g];
    const int tx = threadIdx.x & 31, ty = threadIdx.x >> 5;
    const int n0 = blockIdx.x * 32, k0 = blockIdx.y * 32;
#pragma unroll
    for (int j = 0; j < 4; j++)
        t[ty + j * 8][tx] = W[(size_t)(k0 + ty + j * 8) * NDIM + n0 + tx];
    __syncthreads();
#pragma unroll
    for (int j = 0; j < 4; j++) {
        const float v = t[tx][ty + j * 8];
        const size_t o = (size_t)(g * 1024 + n0 + ty + j * 8) * KDIM + k0 + tx;
        g_Wh[o] = __float2half_rn(v);
    }
}

// ----------------------------------------------------------------------------
// gemm6: BM=BN=128, BK=32, 3 stages, 2 CTAs/SM, single product A@W^T
// ----------------------------------------------------------------------------
#define SSTRIDE 40                      // fp16 elems per smem row (32 data + 8 pad)
#define MAT_ELEMS (128 * SSTRIDE)       // 5120
#define STAGE_ELEMS (2 * MAT_ELEMS)     // A, W
#define NSTAGE 3
#define SMEM_BYTES (NSTAGE * STAGE_ELEMS * 2)   // 61440

__device__ __forceinline__ void cp16(uint32_t dst, const void* src)
{
    asm volatile("cp.async.cg.shared.global [%0], [%1], 16;"
                 :: "r"(dst), "l"(src) : "memory");
}
#define CP_COMMIT() asm volatile("cp.async.commit_group;" ::: "memory")
#define CP_WAIT(n)  asm volatile("cp.async.wait_group %0;" :: "n"(n) : "memory")

__device__ __forceinline__ void ldsm4(uint32_t* d, uint32_t addr)
{
    asm volatile("ldmatrix.sync.aligned.m8n8.x4.shared.b16 {%0,%1,%2,%3}, [%4];"
                 : "=r"(d[0]), "=r"(d[1]), "=r"(d[2]), "=r"(d[3]) : "r"(addr));
}

__device__ __forceinline__ void mma16816(float* c, const uint32_t* a,
                                         const uint32_t* b)
{
    asm volatile(
        "mma.sync.aligned.m16n8k16.row.col.f32.f16.f16.f32 "
        "{%0,%1,%2,%3}, {%4,%5,%6,%7}, {%8,%9}, {%0,%1,%2,%3};"
        : "+f"(c[0]), "+f"(c[1]), "+f"(c[2]), "+f"(c[3])
        : "r"(a[0]), "r"(a[1]), "r"(a[2]), "r"(a[3]), "r"(b[0]), "r"(b[1]));
}

__global__ void __launch_bounds__(256, 2) gemm6()
{
    extern __shared__ __half smem[];
    uint32_t sb;
    asm("{ .reg .u64 t; cvta.to.shared.u64 t, %1; cvt.u32.u64 %0, t; }"
        : "=r"(sb) : "l"(smem));

    const int tid  = threadIdx.x;
    const int lane = tid & 31, wid = tid >> 5;
    const int wm = wid >> 2, wn = wid & 3;          // 2 x 4 warps

    const int g  = blockIdx.z;
    const int bm = blockIdx.y * 128;
    const int bn = blockIdx.x * 128;
    const int arow = ((g & 1) << 12) + bm;
    const int wrow = (g << 10) + bn;

    const __half* gb[2] = {
        g_Ah + (size_t)arow * KDIM, g_Wh + (size_t)wrow * KDIM};

    // per-thread load mapping: 4 chunks of 16B (2 matrices x 512 chunks / 256 thr)
    int l_mat[4], l_row[4], l_ch[4];
#pragma unroll
    for (int i = 0; i < 4; i++) {
        const int idx = tid + i * 256;
        l_mat[i] = idx >> 9;                        // 0..1
        const int wi = idx & 511;
        l_row[i] = wi >> 2;
        l_ch[i]  = wi & 3;
    }

#define LOAD_STAGE(kt, s)                                                      \
    do {                                                                       \
        const uint32_t sbase_ = sb + (uint32_t)(s) * (STAGE_ELEMS * 2);        \
        _Pragma("unroll")                                                      \
        for (int i = 0; i < 4; i++) {                                          \
            const uint32_t dst = sbase_ +                                      \
                (uint32_t)(l_mat[i] * MAT_ELEMS + l_row[i] * SSTRIDE +         \
                           l_ch[i] * 8) * 2;                                   \
            cp16(dst, gb[l_mat[i]] + (size_t)l_row[i] * KDIM +                 \
                      (kt) * 32 + l_ch[i] * 8);                                \
        }                                                                      \
    } while (0)

    float acc[4][4][4];
#pragma unroll
    for (int mt = 0; mt < 4; mt++)
#pragma unroll
        for (int nt = 0; nt < 4; nt++)
#pragma unroll
            for (int j = 0; j < 4; j++) acc[mt][nt][j] = 0.f;

    LOAD_STAGE(0, 0); CP_COMMIT();
    LOAD_STAGE(1, 1); CP_COMMIT();
    LOAD_STAGE(2, 2); CP_COMMIT();

    const int a_r = (lane & 7) + ((lane >> 3) & 1) * 8;
    const int a_c = (lane >> 4) * 8;
    const int b_r = (lane & 7) + (lane >> 4) * 8;
    const int b_c = ((lane >> 3) & 1) * 8;

    for (int kt = 0; kt < 32; kt++) {
        CP_WAIT(2);                       // stage kt resident
        __syncthreads();

        const int slot = kt % 3;
        const uint32_t sbase = sb + (uint32_t)slot * (STAGE_ELEMS * 2);
#pragma unroll
        for (int ks = 0; ks < 2; ks++) {
            uint32_t a[4][4], bq[4][2];
#pragma unroll
            for (int p = 0; p < 2; p++) {
                uint32_t q[4];
                ldsm4(q, sbase + (uint32_t)(MAT_ELEMS +
                        (wn * 32 + p * 16 + b_r) * SSTRIDE + ks * 16 + b_c) * 2);
                bq[2 * p][0] = q[0]; bq[2 * p][1] = q[1];
                bq[2 * p + 1][0] = q[2]; bq[2 * p + 1][1] = q[3];
            }
#pragma unroll
            for (int mt = 0; mt < 4; mt++)
                ldsm4(a[mt], sbase +
                      (uint32_t)((wm * 64 + mt * 16 + a_r) * SSTRIDE +
                                 ks * 16 + a_c) * 2);
#pragma unroll
            for (int mt = 0; mt < 4; mt++)
#pragma unroll
                for (int nt = 0; nt < 4; nt++)
                    mma16816(acc[mt][nt], a[mt], bq[nt]);
        }

        __syncthreads();                  // everyone done reading stage kt
        if (kt + 3 < 32) LOAD_STAGE(kt + 3, slot);
        CP_COMMIT();
    }
    CP_WAIT(0);

    float* Cb = g_C + (size_t)g * GSZ;
    const int mrow = bm + wm * 64 + (lane >> 2);
    const int ncol = bn + wn * 32 + (lane & 3) * 2;
#pragma unroll
    for (int mt = 0; mt < 4; mt++) {
#pragma unroll
        for (int nt = 0; nt < 4; nt++) {
            float* p0 = Cb + (size_t)(mrow + mt * 16) * NDIM + ncol + nt * 8;
            *reinterpret_cast<float2*>(p0) =
                make_float2(acc[mt][nt][0], acc[mt][nt][1]);
            *reinterpret_cast<float2*>(p0 + 8 * NDIM) =
                make_float2(acc[mt][nt][2], acc[mt][nt][3]);
        }
    }
#undef LOAD_STAGE
}

// ----------------------------------------------------------------------------
// hyp_fused — 2-pass Gram (round-9 proven: VPT=4, 256 thr, no launch cap)
// ----------------------------------------------------------------------------
#define RT 256
#define VPT 4

__device__ __forceinline__ float artanh_c(float x)
{
    x = fminf(fmaxf(x, -1.f + 1e-5f), 1.f - 1e-5f);
    return 0.5f * __logf(__fdividef(1.f + x, 1.f - x));
}

__device__ __forceinline__ float tanh_pos(float v)   // v >= 0
{
    return 1.f - __fdividef(2.f, __expf(2.f * v) + 1.f);
}

__device__ __forceinline__ float sigmoid_f(float v)
{
    return __fdividef(1.f, 1.f + __expf(-v));
}

__device__ __forceinline__ void safe_norm(float v2, float& inv_n, float& n)
{
    const float vc = fmaxf(v2, 1e-15f);
    inv_n = rsqrtf(vc);
    n = vc * inv_n;
}

__device__ __forceinline__ float mv_factor(float g2, float inv_xn, float atx)
{
    float inv_gn, gn;
    safe_norm(g2, inv_gn, gn);
    return tanh_pos(gn * inv_xn * atx) * inv_gn;
}

__device__ __forceinline__ void madd_coef(float ab, float a2, float b2,
                                          float& cA, float& cB)
{
    const float inv = __fdividef(1.f, 1.f + 2.f * ab + a2 * b2);
    cA = (1.f + 2.f * ab + b2) * inv;
    cB = (1.f - a2) * inv;
}

template <int N>
__device__ __forceinline__ void blockReduceN(float* v, float* buf)
{
    const int lane = threadIdx.x & 31, wid = threadIdx.x >> 5;
#pragma unroll
    for (int o = 16; o; o >>= 1)
#pragma unroll
        for (int i = 0; i < N; i++)
            v[i] += __shfl_xor_sync(0xffffffffu, v[i], o);
    if (lane == 0)
#pragma unroll
        for (int i = 0; i < N; i++) buf[wid * N + i] = v[i];
    __syncthreads();
#pragma unroll
    for (int i = 0; i < N; i++) {
        float s = 0.f;
#pragma unroll
        for (int w = 0; w < 8; w++) s += buf[w * N + i];
        v[i] = s;
    }
}

__global__ void __launch_bounds__(256) hyp_fused(
    const float* __restrict__ inp, const float* __restrict__ prevh,
    const float* __restrict__ bzp, const float* __restrict__ brp,
    const float* __restrict__ bhp, float* __restrict__ out)
{
    __shared__ float buf1[8 * 19];
    __shared__ float buf2[8 * 12];
    const int tid = threadIdx.x;
    const size_t off = (size_t)blockIdx.x * NDIM;

    float H[VPT], G0[VPT], G1[VPT], G2[VPT], G3[VPT], G4[VPT], G5[VPT];
    float BZ[VPT], BR[VPT], BH[VPT];
    float s[19];
#pragma unroll
    for (int i = 0; i < 19; i++) s[i] = 0.f;

#pragma unroll
    for (int j = 0; j < VPT; j++) {
        const int c = j * RT + tid;
        const float xv = inp[off + c];
        H[j]  = prevh[off + c];
        G0[j] = g_C[0 * GSZ + off + c];
        G1[j] = g_C[1 * GSZ + off + c];
        G2[j] = g_C[2 * GSZ + off + c];
        G3[j] = g_C[3 * GSZ + off + c];
        G4[j] = g_C[4 * GSZ + off + c];
        G5[j] = g_C[5 * GSZ + off + c];
        BZ[j] = bzp[c];
        BR[j] = brp[c];
        BH[j] = bhp[c];
        s[0]  = fmaf(xv, xv, s[0]);
        s[1]  = fmaf(H[j], H[j], s[1]);
        s[2]  = fmaf(G0[j], G0[j], s[2]);
        s[3]  = fmaf(G1[j], G1[j], s[3]);
        s[4]  = fmaf(G0[j], G1[j], s[4]);
        s[5]  = fmaf(G0[j], BZ[j], s[5]);
        s[6]  = fmaf(G1[j], BZ[j], s[6]);
        s[7]  = fmaf(BZ[j], BZ[j], s[7]);
        s[8]  = fmaf(G2[j], G2[j], s[8]);
        s[9]  = fmaf(G3[j], G3[j], s[9]);
        s[10] = fmaf(G2[j], G3[j], s[10]);
        s[11] = fmaf(G2[j], BR[j], s[11]);
        s[12] = fmaf(G3[j], BR[j], s[12]);
        s[13] = fmaf(BR[j], BR[j], s[13]);
        s[14] = fmaf(G5[j], G5[j], s[14]);
        s[15] = fmaf(G5[j], BH[j], s[15]);
        s[16] = fmaf(BH[j], BH[j], s[16]);
        s[17] = fmaf(G4[j], G4[j], s[17]);
        s[18] = fmaf(G4[j], H[j], s[18]);
    }
    blockReduceN<19>(s, buf1);
    const float xx = s[0], hh = s[1];
    const float g00 = s[2], g11 = s[3], g01 = s[4], g0z = s[5], g1z = s[6], zz = s[7];
    const float g22 = s[8], g33 = s[9], g23 = s[10], g2r = s[11], g3r = s[12], rrb = s[13];
    const float g55 = s[14], g5h = s[15], bhbh = s[16], g44 = s[17], g4H = s[18];

    float inv_xn, xn, inv_hn, hn;
    safe_norm(xx, inv_xn, xn);
    safe_norm(hh, inv_hn, hn);
    const float atx = artanh_c(xn);
    const float ath = artanh_c(hn);

    const float t0 = mv_factor(g00, inv_xn, atx);
    const float t1 = mv_factor(g11, inv_hn, ath);
    const float t2 = mv_factor(g22, inv_xn, atx);
    const float t3 = mv_factor(g33, inv_hn, ath);
    const float t4 = mv_factor(g44, inv_xn, atx);
    const float t5 = mv_factor(g55, inv_hn, ath);

    // z gate
    float cA, cB;
    madd_coef(t1 * g1z, t1 * t1 * g11, zz, cA, cB);
    const float u1 = cA * t1, u2 = cB;
    madd_coef(t0 * (u1 * g01 + u2 * g0z), t0 * t0 * g00,
              u1 * u1 * g11 + 2.f * u1 * u2 * g1z + u2 * u2 * zz, cA, cB);
    const float w0 = cA * t0, w1 = cB * u1, w2 = cB * u2;
    {
        const float nz2 = w0 * w0 * g00 + w1 * w1 * g11 + w2 * w2 * zz +
                          2.f * (w0 * w1 * g01 + w0 * w2 * g0z + w1 * w2 * g1z);
        float inv_nz, nz;
        safe_norm(nz2, inv_nz, nz);
        const float fz = artanh_c(nz) * inv_nz;
#pragma unroll
        for (int j = 0; j < VPT; j++)
            G0[j] = sigmoid_f(fz * (w0 * G0[j] + w1 * G1[j] + w2 * BZ[j]));
    }

    // r gate
    madd_coef(t3 * g3r, t3 * t3 * g33, rrb, cA, cB);
    const float v1 = cA * t3, v2 = cB;
    madd_coef(t2 * (v1 * g23 + v2 * g2r), t2 * t2 * g22,
              v1 * v1 * g33 + 2.f * v1 * v2 * g3r + v2 * v2 * rrb, cA, cB);
    const float y0 = cA * t2, y1 = cB * v1, y2 = cB * v2;
    {
        const float nr2 = y0 * y0 * g22 + y1 * y1 * g33 + y2 * y2 * rrb +
                          2.f * (y0 * y1 * g23 + y0 * y2 * g2r + y1 * y2 * g3r);
        float inv_nr, nr;
        safe_norm(nr2, inv_nr, nr);
        const float fr = artanh_c(nr) * inv_nr;
#pragma unroll
        for (int j = 0; j < VPT; j++)
            G1[j] = sigmoid_f(fr * (y0 * G2[j] + y1 * G3[j] + y2 * BR[j]));
    }

    // ahh = d5*G5 + db*BH
    madd_coef(t5 * g5h, t5 * t5 * g55, bhbh, cA, cB);
    const float d5 = cA * t5, db = cB;
    const float ahh2 = d5 * d5 * g55 + 2.f * d5 * db * g5h + db * db * bhbh;

    // pass-2 elementwise prep + sums
    float q[VPT];
    float s2[12];
#pragma unroll
    for (int i = 0; i < 12; i++) s2[i] = 0.f;
#pragma unroll
    for (int j = 0; j < VPT; j++) {
        q[j] = G1[j] * (d5 * G5[j] + db * BH[j]);
        const float z = G0[j];
        const float zh = z * H[j], zq = z * q[j], zg = z * G4[j];
        s2[0]  = fmaf(q[j], q[j], s2[0]);
        s2[1]  = fmaf(q[j], G4[j], s2[1]);
        s2[2]  = fmaf(q[j], H[j], s2[2]);
        s2[3]  = fmaf(zh, zh, s2[3]);
        s2[4]  = fmaf(zh, zq, s2[4]);
        s2[5]  = fmaf(zh, zg, s2[5]);
        s2[6]  = fmaf(zq, zq, s2[6]);
        s2[7]  = fmaf(zq, zg, s2[7]);
        s2[8]  = fmaf(zg, zg, s2[8]);
        s2[9]  = fmaf(H[j], zh, s2[9]);
        s2[10] = fmaf(H[j], zq, s2[10]);
        s2[11] = fmaf(H[j], zg, s2[11]);
    }
    blockReduceN<12>(s2, buf2);
    const float qq = s2[0], qg4 = s2[1], qh = s2[2];
    const float s11 = s2[3], s12 = s2[4], s13 = s2[5];
    const float s22 = s2[6], s23 = s2[7], s33 = s2[8];
    const float hzh = s2[9], hzq = s2[10], hzg4 = s2[11];

    float inv_na, na, inv_nq, nq;
    safe_norm(ahh2, inv_na, na);
    safe_norm(qq, inv_nq, nq);
    const float tp = tanh_pos(nq * inv_na * artanh_c(na)) * inv_nq;

    madd_coef(tp * t4 * qg4, tp * tp * qq, t4 * t4 * g44, cA, cB);
    const float bq = cA * tp, b4 = cB * t4;

    const float temp2 = bq * bq * qq + 2.f * bq * b4 * qg4 + b4 * b4 * g44;
    madd_coef(-(bq * qh + b4 * g4H), hh, temp2, cA, cB);
    const float alpha = -cA, bq2 = cB * bq, b42 = cB * b4;

    const float mh2 = alpha * alpha * hh + bq2 * bq2 * qq + b42 * b42 * g44 +
                      2.f * (alpha * bq2 * qh + alpha * b42 * g4H + bq2 * b42 * qg4);
    const float ux2 = alpha * alpha * s11 + bq2 * bq2 * s22 + b42 * b42 * s33 +
                      2.f * (alpha * bq2 * s12 + alpha * b42 * s13 + bq2 * b42 * s23);
    float inv_nmh, nmh, inv_nux, nux;
    safe_norm(mh2, inv_nmh, nmh);
    safe_norm(ux2, inv_nux, nux);
    const float tz = tanh_pos(nux * inv_nmh * artanh_c(nmh)) * inv_nux;

    madd_coef(tz * (alpha * hzh + bq2 * hzq + b42 * hzg4), hh, tz * tz * ux2,
              cA, cB);
    const float k0 = cA;
    const float kz = cB * tz;
    const float ka = kz * alpha, kb = kz * bq2, kc = kz * b42;

#pragma unroll
    for (int j = 0; j < VPT; j++) {
        const float z = G0[j];
        out[off + j * RT + tid] =
            k0 * H[j] + z * (ka * H[j] + kb * q[j] + kc * G4[j]);
    }
}

// ----------------------------------------------------------------------------
// launch
// ----------------------------------------------------------------------------
extern "C" void kernel_launch(void* const* d_in, const int* in_sizes, int n_in,
                              void* d_out, int out_size)
{
    const float* inp   = (const float*)d_in[0];
    const float* prevh = (const float*)d_in[1];
    WPtrs wp;
    wp.w[0] = (const float*)d_in[2];  // w_inp_z
    wp.w[1] = (const float*)d_in[3];  // w_hid_z
    wp.w[2] = (const float*)d_in[5];  // w_inp_r
    wp.w[3] = (const float*)d_in[6];  // w_hid_r
    wp.w[4] = (const float*)d_in[8];  // w_inp_h
    wp.w[5] = (const float*)d_in[9];  // w_hid_h
    const float* b_z = (const float*)d_in[4];
    const float* b_r = (const float*)d_in[7];
    const float* b_h = (const float*)d_in[10];
    float* out = (float*)d_out;

    cudaFuncSetAttribute(gemm6, cudaFuncAttributeMaxDynamicSharedMemorySize,
                         SMEM_BYTES);

    split_act<<<8192, 256>>>(inp, prevh);
    split_wt<<<dim3(32, 32, 6), 256>>>(wp);
    gemm6<<<dim3(8, 32, 6), 256, SMEM_BYTES>>>();
    hyp_fused<<<MDIM, 256>>>(inp, prevh, b_z, b_r, b_h, out);
}

// round 12
// speedup vs baseline: 1.7588x; 1.0006x over previous
#include <cuda_runtime.h>
#include <cuda_bf16.h>
#include <cuda_fp16.h>
#include <cstdint>

// ============================================================================
// HyperGRUCell — round 12: single-product fp16 GEMM (4-stage) + 2-kernel hyp
//   split_act : fp32 -> fp16 for [inp; prev_h]
//   split_wt  : fp32 W[k][n] -> fp16 Wt[n][k]
//   gemm6     : C = A@W^T (fp32 accum, HMMA, 1 product, 4-stage pipeline)
//   hyp_p1    : Gram pass 1 -> 15 scalars/row      (low liveness, high occ)
//   hyp_p2    : Gram pass 2 -> output              (low liveness, high occ)
// ============================================================================

#define MDIM 4096
#define NDIM 1024
#define KDIM 1024
#define GSZ  ((size_t)MDIM * NDIM)

__device__ float  g_C[6ull * MDIM * NDIM];
__device__ __half g_Ah[8192ull * 1024];
__device__ __half g_Wh[6144ull * 1024];
__device__ float  g_S[4096 * 16];        // per-row pass-1 scalars

// ----------------------------------------------------------------------------
// split kernels
// ----------------------------------------------------------------------------
__global__ void __launch_bounds__(256) split_act(const float* __restrict__ inp,
                                                 const float* __restrict__ prevh)
{
    const size_t i = ((size_t)blockIdx.x * 256 + threadIdx.x) * 4;
    const size_t half = (size_t)MDIM * KDIM;
    const float* src = (i < half) ? (inp + i) : (prevh + (i - half));
    float4 v = *reinterpret_cast<const float4*>(src);
    float x[4] = {v.x, v.y, v.z, v.w};
    uint32_t hp[2];
#pragma unroll
    for (int j = 0; j < 2; j++) {
        __half h0 = __float2half_rn(x[2 * j]);
        __half h1 = __float2half_rn(x[2 * j + 1]);
        hp[j] = (uint32_t)__half_as_ushort(h0) |
                ((uint32_t)__half_as_ushort(h1) << 16);
    }
    *reinterpret_cast<uint2*>(reinterpret_cast<char*>(g_Ah) + i * 2) = make_uint2(hp[0], hp[1]);
}

struct WPtrs { const float* w[6]; };

__global__ void __launch_bounds__(256) split_wt(WPtrs wp)
{
    __shared__ float t[32][33];
    const int g = blockIdx.z;
    const float* __restrict__ W = wp.w[g];
    const int tx = threadIdx.x & 31, ty = threadIdx.x >> 5;
    const int n0 = blockIdx.x * 32, k0 = blockIdx.y * 32;
#pragma unroll
    for (int j = 0; j < 4; j++)
        t[ty + j * 8][tx] = W[(size_t)(k0 + ty + j * 8) * NDIM + n0 + tx];
    __syncthreads();
#pragma unroll
    for (int j = 0; j < 4; j++) {
        const float v = t[tx][ty + j * 8];
        const size_t o = (size_t)(g * 1024 + n0 + ty + j * 8) * KDIM + k0 + tx;
        g_Wh[o] = __float2half_rn(v);
    }
}

// ----------------------------------------------------------------------------
// gemm6: BM=BN=128, BK=32, 4 stages, 2 CTAs/SM, single product A@W^T
// ----------------------------------------------------------------------------
#define SSTRIDE 40
#define MAT_ELEMS (128 * SSTRIDE)
#define STAGE_ELEMS (2 * MAT_ELEMS)
#define NSTAGE 4
#define SMEM_BYTES (NSTAGE * STAGE_ELEMS * 2)   // 81920

__device__ __forceinline__ void cp16(uint32_t dst, const void* src)
{
    asm volatile("cp.async.cg.shared.global [%0], [%1], 16;"
                 :: "r"(dst), "l"(src) : "memory");
}
#define CP_COMMIT() asm volatile("cp.async.commit_group;" ::: "memory")
#define CP_WAIT(n)  asm volatile("cp.async.wait_group %0;" :: "n"(n) : "memory")

__device__ __forceinline__ void ldsm4(uint32_t* d, uint32_t addr)
{
    asm volatile("ldmatrix.sync.aligned.m8n8.x4.shared.b16 {%0,%1,%2,%3}, [%4];"
                 : "=r"(d[0]), "=r"(d[1]), "=r"(d[2]), "=r"(d[3]) : "r"(addr));
}

__device__ __forceinline__ void mma16816(float* c, const uint32_t* a,
                                         const uint32_t* b)
{
    asm volatile(
        "mma.sync.aligned.m16n8k16.row.col.f32.f16.f16.f32 "
        "{%0,%1,%2,%3}, {%4,%5,%6,%7}, {%8,%9}, {%0,%1,%2,%3};"
        : "+f"(c[0]), "+f"(c[1]), "+f"(c[2]), "+f"(c[3])
        : "r"(a[0]), "r"(a[1]), "r"(a[2]), "r"(a[3]), "r"(b[0]), "r"(b[1]));
}

__global__ void __launch_bounds__(256, 2) gemm6()
{
    extern __shared__ __half smem[];
    uint32_t sb;
    asm("{ .reg .u64 t; cvta.to.shared.u64 t, %1; cvt.u32.u64 %0, t; }"
        : "=r"(sb) : "l"(smem));

    const int tid  = threadIdx.x;
    const int lane = tid & 31, wid = tid >> 5;
    const int wm = wid >> 2, wn = wid & 3;

    const int g  = blockIdx.z;
    const int bm = blockIdx.y * 128;
    const int bn = blockIdx.x * 128;
    const int arow = ((g & 1) << 12) + bm;
    const int wrow = (g << 10) + bn;

    const __half* gb[2] = {
        g_Ah + (size_t)arow * KDIM, g_Wh + (size_t)wrow * KDIM};

    int l_mat[4], l_row[4], l_ch[4];
#pragma unroll
    for (int i = 0; i < 4; i++) {
        const int idx = tid + i * 256;
        l_mat[i] = idx >> 9;
        const int wi = idx & 511;
        l_row[i] = wi >> 2;
        l_ch[i]  = wi & 3;
    }

#define LOAD_STAGE(kt, s)                                                      \
    do {                                                                       \
        const uint32_t sbase_ = sb + (uint32_t)(s) * (STAGE_ELEMS * 2);        \
        _Pragma("unroll")                                                      \
        for (int i = 0; i < 4; i++) {                                          \
            const uint32_t dst = sbase_ +                                      \
                (uint32_t)(l_mat[i] * MAT_ELEMS + l_row[i] * SSTRIDE +         \
                           l_ch[i] * 8) * 2;                                   \
            cp16(dst, gb[l_mat[i]] + (size_t)l_row[i] * KDIM +                 \
                      (kt) * 32 + l_ch[i] * 8);                                \
        }                                                                      \
    } while (0)

    float acc[4][4][4];
#pragma unroll
    for (int mt = 0; mt < 4; mt++)
#pragma unroll
        for (int nt = 0; nt < 4; nt++)
#pragma unroll
            for (int j = 0; j < 4; j++) acc[mt][nt][j] = 0.f;

    LOAD_STAGE(0, 0); CP_COMMIT();
    LOAD_STAGE(1, 1); CP_COMMIT();
    LOAD_STAGE(2, 2); CP_COMMIT();
    LOAD_STAGE(3, 3); CP_COMMIT();

    const int a_r = (lane & 7) + ((lane >> 3) & 1) * 8;
    const int a_c = (lane >> 4) * 8;
    const int b_r = (lane & 7) + (lane >> 4) * 8;
    const int b_c = ((lane >> 3) & 1) * 8;

    for (int kt = 0; kt < 32; kt++) {
        CP_WAIT(3);
        __syncthreads();

        const int slot = kt & 3;
        const uint32_t sbase = sb + (uint32_t)slot * (STAGE_ELEMS * 2);
#pragma unroll
        for (int ks = 0; ks < 2; ks++) {
            uint32_t a[4][4], bq[4][2];
#pragma unroll
            for (int p = 0; p < 2; p++) {
                uint32_t q[4];
                ldsm4(q, sbase + (uint32_t)(MAT_ELEMS +
                        (wn * 32 + p * 16 + b_r) * SSTRIDE + ks * 16 + b_c) * 2);
                bq[2 * p][0] = q[0]; bq[2 * p][1] = q[1];
                bq[2 * p + 1][0] = q[2]; bq[2 * p + 1][1] = q[3];
            }
#pragma unroll
            for (int mt = 0; mt < 4; mt++)
                ldsm4(a[mt], sbase +
                      (uint32_t)((wm * 64 + mt * 16 + a_r) * SSTRIDE +
                                 ks * 16 + a_c) * 2);
#pragma unroll
            for (int mt = 0; mt < 4; mt++)
#pragma unroll
                for (int nt = 0; nt < 4; nt++)
                    mma16816(acc[mt][nt], a[mt], bq[nt]);
        }

        __syncthreads();
        if (kt + 4 < 32) LOAD_STAGE(kt + 4, slot);
        CP_COMMIT();
    }
    CP_WAIT(0);

    float* Cb = g_C + (size_t)g * GSZ;
    const int mrow = bm + wm * 64 + (lane >> 2);
    const int ncol = bn + wn * 32 + (lane & 3) * 2;
#pragma unroll
    for (int mt = 0; mt < 4; mt++) {
#pragma unroll
        for (int nt = 0; nt < 4; nt++) {
            float* p0 = Cb + (size_t)(mrow + mt * 16) * NDIM + ncol + nt * 8;
            *reinterpret_cast<float2*>(p0) =
                make_float2(acc[mt][nt][0], acc[mt][nt][1]);
            *reinterpret_cast<float2*>(p0 + 8 * NDIM) =
                make_float2(acc[mt][nt][2], acc[mt][nt][3]);
        }
    }
#undef LOAD_STAGE
}

// ----------------------------------------------------------------------------
// hyperbolic math helpers
// ----------------------------------------------------------------------------
#define RT 256
#define VPT 4

__device__ __forceinline__ float artanh_c(float x)
{
    x = fminf(fmaxf(x, -1.f + 1e-5f), 1.f - 1e-5f);
    return 0.5f * __logf(__fdividef(1.f + x, 1.f - x));
}

__device__ __forceinline__ float tanh_pos(float v)   // v >= 0
{
    return 1.f - __fdividef(2.f, __expf(2.f * v) + 1.f);
}

__device__ __forceinline__ float sigmoid_f(float v)
{
    return __fdividef(1.f, 1.f + __expf(-v));
}

__device__ __forceinline__ void safe_norm(float v2, float& inv_n, float& n)
{
    const float vc = fmaxf(v2, 1e-15f);
    inv_n = rsqrtf(vc);
    n = vc * inv_n;
}

__device__ __forceinline__ float mv_factor(float g2, float inv_xn, float atx)
{
    float inv_gn, gn;
    safe_norm(g2, inv_gn, gn);
    return tanh_pos(gn * inv_xn * atx) * inv_gn;
}

__device__ __forceinline__ void madd_coef(float ab, float a2, float b2,
                                          float& cA, float& cB)
{
    const float inv = __fdividef(1.f, 1.f + 2.f * ab + a2 * b2);
    cA = (1.f + 2.f * ab + b2) * inv;
    cB = (1.f - a2) * inv;
}

template <int N>
__device__ __forceinline__ void blockReduceN(float* v, float* buf)
{
    const int lane = threadIdx.x & 31, wid = threadIdx.x >> 5;
#pragma unroll
    for (int o = 16; o; o >>= 1)
#pragma unroll
        for (int i = 0; i < N; i++)
            v[i] += __shfl_xor_sync(0xffffffffu, v[i], o);
    if (lane == 0)
#pragma unroll
        for (int i = 0; i < N; i++) buf[wid * N + i] = v[i];
    __syncthreads();
#pragma unroll
    for (int i = 0; i < N; i++) {
        float s = 0.f;
#pragma unroll
        for (int w = 0; w < 8; w++) s += buf[w * N + i];
        v[i] = s;
    }
}

// ----------------------------------------------------------------------------
// hyp_p1: Gram pass 1 -> 15 scalars per row
// ----------------------------------------------------------------------------
__global__ void __launch_bounds__(256) hyp_p1(
    const float* __restrict__ inp, const float* __restrict__ prevh,
    const float* __restrict__ bzp, const float* __restrict__ brp,
    const float* __restrict__ bhp)
{
    __shared__ float buf[8 * 19];
    const int tid = threadIdx.x;
    const size_t off = (size_t)blockIdx.x * NDIM;

    float s[19];
#pragma unroll
    for (int i = 0; i < 19; i++) s[i] = 0.f;

#pragma unroll
    for (int j = 0; j < VPT; j++) {
        const int c = j * RT + tid;
        const float xv = inp[off + c];
        const float h  = prevh[off + c];
        const float g0 = g_C[0 * GSZ + off + c];
        const float g1 = g_C[1 * GSZ + off + c];
        const float g2 = g_C[2 * GSZ + off + c];
        const float g3 = g_C[3 * GSZ + off + c];
        const float g4 = g_C[4 * GSZ + off + c];
        const float g5 = g_C[5 * GSZ + off + c];
        const float bz = bzp[c];
        const float br = brp[c];
        const float bh = bhp[c];
        s[0]  = fmaf(xv, xv, s[0]);
        s[1]  = fmaf(h, h, s[1]);
        s[2]  = fmaf(g0, g0, s[2]);
        s[3]  = fmaf(g1, g1, s[3]);
        s[4]  = fmaf(g0, g1, s[4]);
        s[5]  = fmaf(g0, bz, s[5]);
        s[6]  = fmaf(g1, bz, s[6]);
        s[7]  = fmaf(bz, bz, s[7]);
        s[8]  = fmaf(g2, g2, s[8]);
        s[9]  = fmaf(g3, g3, s[9]);
        s[10] = fmaf(g2, g3, s[10]);
        s[11] = fmaf(g2, br, s[11]);
        s[12] = fmaf(g3, br, s[12]);
        s[13] = fmaf(br, br, s[13]);
        s[14] = fmaf(g5, g5, s[14]);
        s[15] = fmaf(g5, bh, s[15]);
        s[16] = fmaf(bh, bh, s[16]);
        s[17] = fmaf(g4, g4, s[17]);
        s[18] = fmaf(g4, h, s[18]);
    }
    blockReduceN<19>(s, buf);
    if (tid >= 32) return;          // scalar algebra on one warp only

    const float xx = s[0], hh = s[1];
    const float g00 = s[2], g11 = s[3], g01 = s[4], g0z = s[5], g1z = s[6], zz = s[7];
    const float g22 = s[8], g33 = s[9], g23 = s[10], g2r = s[11], g3r = s[12], rrb = s[13];
    const float g55 = s[14], g5h = s[15], bhbh = s[16], g44 = s[17], g4H = s[18];

    float inv_xn, xn, inv_hn, hn;
    safe_norm(xx, inv_xn, xn);
    safe_norm(hh, inv_hn, hn);
    const float atx = artanh_c(xn);
    const float ath = artanh_c(hn);

    const float t0 = mv_factor(g00, inv_xn, atx);
    const float t1 = mv_factor(g11, inv_hn, ath);
    const float t2 = mv_factor(g22, inv_xn, atx);
    const float t3 = mv_factor(g33, inv_hn, ath);
    const float t4 = mv_factor(g44, inv_xn, atx);
    const float t5 = mv_factor(g55, inv_hn, ath);

    float cA, cB;
    // z gate coefficients
    madd_coef(t1 * g1z, t1 * t1 * g11, zz, cA, cB);
    const float u1 = cA * t1, u2 = cB;
    madd_coef(t0 * (u1 * g01 + u2 * g0z), t0 * t0 * g00,
              u1 * u1 * g11 + 2.f * u1 * u2 * g1z + u2 * u2 * zz, cA, cB);
    const float w0 = cA * t0, w1 = cB * u1, w2 = cB * u2;
    const float nz2 = w0 * w0 * g00 + w1 * w1 * g11 + w2 * w2 * zz +
                      2.f * (w0 * w1 * g01 + w0 * w2 * g0z + w1 * w2 * g1z);
    float inv_nz, nz;
    safe_norm(nz2, inv_nz, nz);
    const float fz = artanh_c(nz) * inv_nz;

    // r gate coefficients
    madd_coef(t3 * g3r, t3 * t3 * g33, rrb, cA, cB);
    const float v1 = cA * t3, v2 = cB;
    madd_coef(t2 * (v1 * g23 + v2 * g2r), t2 * t2 * g22,
              v1 * v1 * g33 + 2.f * v1 * v2 * g3r + v2 * v2 * rrb, cA, cB);
    const float y0 = cA * t2, y1 = cB * v1, y2 = cB * v2;
    const float nr2 = y0 * y0 * g22 + y1 * y1 * g33 + y2 * y2 * rrb +
                      2.f * (y0 * y1 * g23 + y0 * y2 * g2r + y1 * y2 * g3r);
    float inv_nr, nr;
    safe_norm(nr2, inv_nr, nr);
    const float fr = artanh_c(nr) * inv_nr;

    // ahh coefficients
    madd_coef(t5 * g5h, t5 * t5 * g55, bhbh, cA, cB);
    const float d5 = cA * t5, db = cB;
    const float ahh2 = d5 * d5 * g55 + 2.f * d5 * db * g5h + db * db * bhbh;

    if (tid == 0) {
        float* S = g_S + blockIdx.x * 16;
        S[0] = w0;  S[1] = w1;  S[2] = w2;  S[3] = fz;
        S[4] = y0;  S[5] = y1;  S[6] = y2;  S[7] = fr;
        S[8] = d5;  S[9] = db;  S[10] = t4; S[11] = ahh2;
        S[12] = hh; S[13] = g44; S[14] = g4H;
    }
}

// ----------------------------------------------------------------------------
// hyp_p2: Gram pass 2 -> output
// ----------------------------------------------------------------------------
__global__ void __launch_bounds__(256) hyp_p2(
    const float* __restrict__ prevh,
    const float* __restrict__ bzp, const float* __restrict__ brp,
    const float* __restrict__ bhp, float* __restrict__ out)
{
    __shared__ float buf[8 * 12];
    const int tid = threadIdx.x;
    const size_t off = (size_t)blockIdx.x * NDIM;
    const float* __restrict__ S = g_S + blockIdx.x * 16;

    const float w0 = S[0], w1 = S[1], w2 = S[2], fz = S[3];
    const float y0 = S[4], y1 = S[5], y2 = S[6], fr = S[7];
    const float d5 = S[8], db = S[9], t4 = S[10], ahh2 = S[11];
    const float hh = S[12], g44 = S[13], g4H = S[14];

    float z[VPT], q[VPT], H[VPT], G4[VPT];
    float s2[12];
#pragma unroll
    for (int i = 0; i < 12; i++) s2[i] = 0.f;

#pragma unroll
    for (int j = 0; j < VPT; j++) {
        const int c = j * RT + tid;
        const float g0 = g_C[0 * GSZ + off + c];
        const float g1 = g_C[1 * GSZ + off + c];
        z[j] = sigmoid_f(fz * (w0 * g0 + w1 * g1 + w2 * bzp[c]));
        const float g2 = g_C[2 * GSZ + off + c];
        const float g3 = g_C[3 * GSZ + off + c];
        const float rv = sigmoid_f(fr * (y0 * g2 + y1 * g3 + y2 * brp[c]));
        const float g5 = g_C[5 * GSZ + off + c];
        q[j] = rv * (d5 * g5 + db * bhp[c]);
        G4[j] = g_C[4 * GSZ + off + c];
        H[j]  = prevh[off + c];
        const float zh = z[j] * H[j], zq = z[j] * q[j], zg = z[j] * G4[j];
        s2[0]  = fmaf(q[j], q[j], s2[0]);
        s2[1]  = fmaf(q[j], G4[j], s2[1]);
        s2[2]  = fmaf(q[j], H[j], s2[2]);
        s2[3]  = fmaf(zh, zh, s2[3]);
        s2[4]  = fmaf(zh, zq, s2[4]);
        s2[5]  = fmaf(zh, zg, s2[5]);
        s2[6]  = fmaf(zq, zq, s2[6]);
        s2[7]  = fmaf(zq, zg, s2[7]);
        s2[8]  = fmaf(zg, zg, s2[8]);
        s2[9]  = fmaf(H[j], zh, s2[9]);
        s2[10] = fmaf(H[j], zq, s2[10]);
        s2[11] = fmaf(H[j], zg, s2[11]);
    }
    blockReduceN<12>(s2, buf);
    const float qq = s2[0], qg4 = s2[1], qh = s2[2];
    const float s11 = s2[3], s12 = s2[4], s13 = s2[5];
    const float s22 = s2[6], s23 = s2[7], s33 = s2[8];
    const float hzh = s2[9], hzq = s2[10], hzg4 = s2[11];

    float cA, cB;
    float inv_na, na, inv_nq, nq;
    safe_norm(ahh2, inv_na, na);
    safe_norm(qq, inv_nq, nq);
    const float tp = tanh_pos(nq * inv_na * artanh_c(na)) * inv_nq;

    madd_coef(tp * t4 * qg4, tp * tp * qq, t4 * t4 * g44, cA, cB);
    const float bq = cA * tp, b4 = cB * t4;

    const float temp2 = bq * bq * qq + 2.f * bq * b4 * qg4 + b4 * b4 * g44;
    madd_coef(-(bq * qh + b4 * g4H), hh, temp2, cA, cB);
    const float alpha = -cA, bq2 = cB * bq, b42 = cB * b4;

    const float mh2 = alpha * alpha * hh + bq2 * bq2 * qq + b42 * b42 * g44 +
                      2.f * (alpha * bq2 * qh + alpha * b42 * g4H + bq2 * b42 * qg4);
    const float ux2 = alpha * alpha * s11 + bq2 * bq2 * s22 + b42 * b42 * s33 +
                      2.f * (alpha * bq2 * s12 + alpha * b42 * s13 + bq2 * b42 * s23);
    float inv_nmh, nmh, inv_nux, nux;
    safe_norm(mh2, inv_nmh, nmh);
    safe_norm(ux2, inv_nux, nux);
    const float tz = tanh_pos(nux * inv_nmh * artanh_c(nmh)) * inv_nux;

    madd_coef(tz * (alpha * hzh + bq2 * hzq + b42 * hzg4), hh, tz * tz * ux2,
              cA, cB);
    const float k0 = cA;
    const float kz = cB * tz;
    const float ka = kz * alpha, kb = kz * bq2, kc = kz * b42;

#pragma unroll
    for (int j = 0; j < VPT; j++)
        out[off + j * RT + tid] =
            k0 * H[j] + z[j] * (ka * H[j] + kb * q[j] + kc * G4[j]);
}

// ----------------------------------------------------------------------------
// launch
// ----------------------------------------------------------------------------
extern "C" void kernel_launch(void* const* d_in, const int* in_sizes, int n_in,
                              void* d_out, int out_size)
{
    const float* inp   = (const float*)d_in[0];
    const float* prevh = (const float*)d_in[1];
    WPtrs wp;
    wp.w[0] = (const float*)d_in[2];  // w_inp_z
    wp.w[1] = (const float*)d_in[3];  // w_hid_z
    wp.w[2] = (const float*)d_in[5];  // w_inp_r
    wp.w[3] = (const float*)d_in[6];  // w_hid_r
    wp.w[4] = (const float*)d_in[8];  // w_inp_h
    wp.w[5] = (const float*)d_in[9];  // w_hid_h
    const float* b_z = (const float*)d_in[4];
    const float* b_r = (const float*)d_in[7];
    const float* b_h = (const float*)d_in[10];
    float* out = (float*)d_out;

    cudaFuncSetAttribute(gemm6, cudaFuncAttributeMaxDynamicSharedMemorySize,
                         SMEM_BYTES);

    split_act<<<8192, 256>>>(inp, prevh);
    split_wt<<<dim3(32, 32, 6), 256>>>(wp);
    gemm6<<<dim3(8, 32, 6), 256, SMEM_BYTES>>>();
    hyp_p1<<<MDIM, 256>>>(inp, prevh, b_z, b_r, b_h);
    hyp_p2<<<MDIM, 256>>>(prevh, b_z, b_r, b_h, out);
}

// round 14
// speedup vs baseline: 1.9087x; 1.0852x over previous
#include <cuda_runtime.h>
#include <cuda_bf16.h>
#include <cuda_fp16.h>
#include <cstdint>

// ============================================================================
// HyperGRUCell — round 14 (= round 13 resubmitted; broker infra failure)
//   split_act : fp32 -> fp16 for [inp; prev_h]
//   split_wt  : fp32 W[k][n] -> fp16 Wt[n][k]
//   gemm6     : C(fp16) = A@W^T (fp32 accum, HMMA, BK=64, 2-stage, 2 CTA/SM)
//   hyp_p1    : Gram pass 1 -> 15 scalars/row
//   hyp_p2    : Gram pass 2 -> output
// ============================================================================

#define MDIM 4096
#define NDIM 1024
#define KDIM 1024
#define GSZ  ((size_t)MDIM * NDIM)

__device__ __half g_C[6ull * MDIM * NDIM];      // fp16 C (48 MB)
__device__ __half g_Ah[8192ull * 1024];
__device__ __half g_Wh[6144ull * 1024];
__device__ float  g_S[4096 * 16];               // per-row pass-1 scalars

// ----------------------------------------------------------------------------
// split kernels
// ----------------------------------------------------------------------------
__global__ void __launch_bounds__(256) split_act(const float* __restrict__ inp,
                                                 const float* __restrict__ prevh)
{
    const size_t i = ((size_t)blockIdx.x * 256 + threadIdx.x) * 4;
    const size_t half = (size_t)MDIM * KDIM;
    const float* src = (i < half) ? (inp + i) : (prevh + (i - half));
    float4 v = *reinterpret_cast<const float4*>(src);
    float x[4] = {v.x, v.y, v.z, v.w};
    uint32_t hp[2];
#pragma unroll
    for (int j = 0; j < 2; j++) {
        __half h0 = __float2half_rn(x[2 * j]);
        __half h1 = __float2half_rn(x[2 * j + 1]);
        hp[j] = (uint32_t)__half_as_ushort(h0) |
                ((uint32_t)__half_as_ushort(h1) << 16);
    }
    *reinterpret_cast<uint2*>(reinterpret_cast<char*>(g_Ah) + i * 2) = make_uint2(hp[0], hp[1]);
}

struct WPtrs { const float* w[6]; };

__global__ void __launch_bounds__(256) split_wt(WPtrs wp)
{
    __shared__ float t[32][33];
    const int g = blockIdx.z;
    const float* __restrict__ W = wp.w[g];
    const int tx = threadIdx.x & 31, ty = threadIdx.x >> 5;
    const int n0 = blockIdx.x * 32, k0 = blockIdx.y * 32;
#pragma unroll
    for (int j = 0; j < 4; j++)
        t[ty + j * 8][tx] = W[(size_t)(k0 + ty + j * 8) * NDIM + n0 + tx];
    __syncthreads();
#pragma unroll
    for (int j = 0; j < 4; j++) {
        const float v = t[tx][ty + j * 8];
        const size_t o = (size_t)(g * 1024 + n0 + ty + j * 8) * KDIM + k0 + tx;
        g_Wh[o] = __float2half_rn(v);
    }
}

// ----------------------------------------------------------------------------
// gemm6: BM=BN=128, BK=64, 2 stages, 2 CTAs/SM, single product A@W^T, fp16 out
// ----------------------------------------------------------------------------
#define SSTRIDE 72                      // 64 data + 8 pad halfs (144 B, 16B-aligned)
#define MAT_ELEMS (128 * SSTRIDE)       // 9216
#define STAGE_ELEMS (2 * MAT_ELEMS)     // A, W
#define NSTAGE 2
#define SMEM_BYTES (NSTAGE * STAGE_ELEMS * 2)   // 73728

__device__ __forceinline__ void cp16(uint32_t dst, const void* src)
{
    asm volatile("cp.async.cg.shared.global [%0], [%1], 16;"
                 :: "r"(dst), "l"(src) : "memory");
}
#define CP_COMMIT() asm volatile("cp.async.commit_group;" ::: "memory")
#define CP_WAIT(n)  asm volatile("cp.async.wait_group %0;" :: "n"(n) : "memory")

__device__ __forceinline__ void ldsm4(uint32_t* d, uint32_t addr)
{
    asm volatile("ldmatrix.sync.aligned.m8n8.x4.shared.b16 {%0,%1,%2,%3}, [%4];"
                 : "=r"(d[0]), "=r"(d[1]), "=r"(d[2]), "=r"(d[3]) : "r"(addr));
}

__device__ __forceinline__ void mma16816(float* c, const uint32_t* a,
                                         const uint32_t* b)
{
    asm volatile(
        "mma.sync.aligned.m16n8k16.row.col.f32.f16.f16.f32 "
        "{%0,%1,%2,%3}, {%4,%5,%6,%7}, {%8,%9}, {%0,%1,%2,%3};"
        : "+f"(c[0]), "+f"(c[1]), "+f"(c[2]), "+f"(c[3])
        : "r"(a[0]), "r"(a[1]), "r"(a[2]), "r"(a[3]), "r"(b[0]), "r"(b[1]));
}

__global__ void __launch_bounds__(256, 2) gemm6()
{
    extern __shared__ __half smem[];
    uint32_t sb;
    asm("{ .reg .u64 t; cvta.to.shared.u64 t, %1; cvt.u32.u64 %0, t; }"
        : "=r"(sb) : "l"(smem));

    const int tid  = threadIdx.x;
    const int lane = tid & 31, wid = tid >> 5;
    const int wm = wid >> 2, wn = wid & 3;          // 2 x 4 warps

    const int g  = blockIdx.z;
    const int bm = blockIdx.y * 128;
    const int bn = blockIdx.x * 128;
    const int arow = ((g & 1) << 12) + bm;
    const int wrow = (g << 10) + bn;

    const __half* gb[2] = {
        g_Ah + (size_t)arow * KDIM, g_Wh + (size_t)wrow * KDIM};

    // per-thread load mapping: 8 chunks of 16B (2 matrices x 1024 chunks / 256 thr)
    int l_mat[8], l_row[8], l_ch[8];
#pragma unroll
    for (int i = 0; i < 8; i++) {
        const int idx = tid + i * 256;
        l_mat[i] = idx >> 10;                       // 0..1
        const int wi = idx & 1023;
        l_row[i] = wi >> 3;                         // 0..127
        l_ch[i]  = wi & 7;                          // 0..7 (8 x 16B = 64 halfs)
    }

#define LOAD_STAGE(kt, s)                                                      \
    do {                                                                       \
        const uint32_t sbase_ = sb + (uint32_t)(s) * (STAGE_ELEMS * 2);        \
        _Pragma("unroll")                                                      \
        for (int i = 0; i < 8; i++) {                                          \
            const uint32_t dst = sbase_ +                                      \
                (uint32_t)(l_mat[i] * MAT_ELEMS + l_row[i] * SSTRIDE +         \
                           l_ch[i] * 8) * 2;                                   \
            cp16(dst, gb[l_mat[i]] + (size_t)l_row[i] * KDIM +                 \
                      (kt) * 64 + l_ch[i] * 8);                                \
        }                                                                      \
    } while (0)

    float acc[4][4][4];
#pragma unroll
    for (int mt = 0; mt < 4; mt++)
#pragma unroll
        for (int nt = 0; nt < 4; nt++)
#pragma unroll
            for (int j = 0; j < 4; j++) acc[mt][nt][j] = 0.f;

    LOAD_STAGE(0, 0); CP_COMMIT();
    LOAD_STAGE(1, 1); CP_COMMIT();

    const int a_r = (lane & 7) + ((lane >> 3) & 1) * 8;
    const int a_c = (lane >> 4) * 8;
    const int b_r = (lane & 7) + (lane >> 4) * 8;
    const int b_c = ((lane >> 3) & 1) * 8;

    for (int kt = 0; kt < 16; kt++) {
        CP_WAIT(1);
        __syncthreads();

        const uint32_t sbase = sb + (uint32_t)(kt & 1) * (STAGE_ELEMS * 2);
#pragma unroll
        for (int ks = 0; ks < 4; ks++) {
            uint32_t a[4][4], bq[4][2];
#pragma unroll
            for (int p = 0; p < 2; p++) {
                uint32_t q[4];
                ldsm4(q, sbase + (uint32_t)(MAT_ELEMS +
                        (wn * 32 + p * 16 + b_r) * SSTRIDE + ks * 16 + b_c) * 2);
                bq[2 * p][0] = q[0]; bq[2 * p][1] = q[1];
                bq[2 * p + 1][0] = q[2]; bq[2 * p + 1][1] = q[3];
            }
#pragma unroll
            for (int mt = 0; mt < 4; mt++)
                ldsm4(a[mt], sbase +
                      (uint32_t)((wm * 64 + mt * 16 + a_r) * SSTRIDE +
                                 ks * 16 + a_c) * 2);
#pragma unroll
            for (int mt = 0; mt < 4; mt++)
#pragma unroll
                for (int nt = 0; nt < 4; nt++)
                    mma16816(acc[mt][nt], a[mt], bq[nt]);
        }

        __syncthreads();
        if (kt + 2 < 16) LOAD_STAGE(kt + 2, kt & 1);
        CP_COMMIT();
    }
    CP_WAIT(0);

    // epilogue: fp32 acc -> fp16 C
    __half* Cb = g_C + (size_t)g * GSZ;
    const int mrow = bm + wm * 64 + (lane >> 2);
    const int ncol = bn + wn * 32 + (lane & 3) * 2;
#pragma unroll
    for (int mt = 0; mt < 4; mt++) {
#pragma unroll
        for (int nt = 0; nt < 4; nt++) {
            __half* p0 = Cb + (size_t)(mrow + mt * 16) * NDIM + ncol + nt * 8;
            *reinterpret_cast<__half2*>(p0) =
                __floats2half2_rn(acc[mt][nt][0], acc[mt][nt][1]);
            *reinterpret_cast<__half2*>(p0 + 8 * NDIM) =
                __floats2half2_rn(acc[mt][nt][2], acc[mt][nt][3]);
        }
    }
#undef LOAD_STAGE
}

// ----------------------------------------------------------------------------
// hyperbolic math helpers
// ----------------------------------------------------------------------------
#define RT 256
#define VPT 4

__device__ __forceinline__ float artanh_c(float x)
{
    x = fminf(fmaxf(x, -1.f + 1e-5f), 1.f - 1e-5f);
    return 0.5f * __logf(__fdividef(1.f + x, 1.f - x));
}

__device__ __forceinline__ float tanh_pos(float v)   // v >= 0
{
    return 1.f - __fdividef(2.f, __expf(2.f * v) + 1.f);
}

__device__ __forceinline__ float sigmoid_f(float v)
{
    return __fdividef(1.f, 1.f + __expf(-v));
}

__device__ __forceinline__ void safe_norm(float v2, float& inv_n, float& n)
{
    const float vc = fmaxf(v2, 1e-15f);
    inv_n = rsqrtf(vc);
    n = vc * inv_n;
}

__device__ __forceinline__ float mv_factor(float g2, float inv_xn, float atx)
{
    float inv_gn, gn;
    safe_norm(g2, inv_gn, gn);
    return tanh_pos(gn * inv_xn * atx) * inv_gn;
}

__device__ __forceinline__ void madd_coef(float ab, float a2, float b2,
                                          float& cA, float& cB)
{
    const float inv = __fdividef(1.f, 1.f + 2.f * ab + a2 * b2);
    cA = (1.f + 2.f * ab + b2) * inv;
    cB = (1.f - a2) * inv;
}

template <int N>
__device__ __forceinline__ void blockReduceN(float* v, float* buf)
{
    const int lane = threadIdx.x & 31, wid = threadIdx.x >> 5;
#pragma unroll
    for (int o = 16; o; o >>= 1)
#pragma unroll
        for (int i = 0; i < N; i++)
            v[i] += __shfl_xor_sync(0xffffffffu, v[i], o);
    if (lane == 0)
#pragma unroll
        for (int i = 0; i < N; i++) buf[wid * N + i] = v[i];
    __syncthreads();
#pragma unroll
    for (int i = 0; i < N; i++) {
        float s = 0.f;
#pragma unroll
        for (int w = 0; w < 8; w++) s += buf[w * N + i];
        v[i] = s;
    }
}

// ----------------------------------------------------------------------------
// hyp_p1: Gram pass 1 -> 15 scalars per row
// ----------------------------------------------------------------------------
__global__ void __launch_bounds__(256) hyp_p1(
    const float* __restrict__ inp, const float* __restrict__ prevh,
    const float* __restrict__ bzp, const float* __restrict__ brp,
    const float* __restrict__ bhp)
{
    __shared__ float buf[8 * 19];
    const int tid = threadIdx.x;
    const size_t off = (size_t)blockIdx.x * NDIM;

    float s[19];
#pragma unroll
    for (int i = 0; i < 19; i++) s[i] = 0.f;

#pragma unroll
    for (int j = 0; j < VPT; j++) {
        const int c = j * RT + tid;
        const float xv = inp[off + c];
        const float h  = prevh[off + c];
        const float g0 = __half2float(g_C[0 * GSZ + off + c]);
        const float g1 = __half2float(g_C[1 * GSZ + off + c]);
        const float g2 = __half2float(g_C[2 * GSZ + off + c]);
        const float g3 = __half2float(g_C[3 * GSZ + off + c]);
        const float g4 = __half2float(g_C[4 * GSZ + off + c]);
        const float g5 = __half2float(g_C[5 * GSZ + off + c]);
        const float bz = bzp[c];
        const float br = brp[c];
        const float bh = bhp[c];
        s[0]  = fmaf(xv, xv, s[0]);
        s[1]  = fmaf(h, h, s[1]);
        s[2]  = fmaf(g0, g0, s[2]);
        s[3]  = fmaf(g1, g1, s[3]);
        s[4]  = fmaf(g0, g1, s[4]);
        s[5]  = fmaf(g0, bz, s[5]);
        s[6]  = fmaf(g1, bz, s[6]);
        s[7]  = fmaf(bz, bz, s[7]);
        s[8]  = fmaf(g2, g2, s[8]);
        s[9]  = fmaf(g3, g3, s[9]);
        s[10] = fmaf(g2, g3, s[10]);
        s[11] = fmaf(g2, br, s[11]);
        s[12] = fmaf(g3, br, s[12]);
        s[13] = fmaf(br, br, s[13]);
        s[14] = fmaf(g5, g5, s[14]);
        s[15] = fmaf(g5, bh, s[15]);
        s[16] = fmaf(bh, bh, s[16]);
        s[17] = fmaf(g4, g4, s[17]);
        s[18] = fmaf(g4, h, s[18]);
    }
    blockReduceN<19>(s, buf);
    if (tid >= 32) return;

    const float xx = s[0], hh = s[1];
    const float g00 = s[2], g11 = s[3], g01 = s[4], g0z = s[5], g1z = s[6], zz = s[7];
    const float g22 = s[8], g33 = s[9], g23 = s[10], g2r = s[11], g3r = s[12], rrb = s[13];
    const float g55 = s[14], g5h = s[15], bhbh = s[16], g44 = s[17], g4H = s[18];

    float inv_xn, xn, inv_hn, hn;
    safe_norm(xx, inv_xn, xn);
    safe_norm(hh, inv_hn, hn);
    const float atx = artanh_c(xn);
    const float ath = artanh_c(hn);

    const float t0 = mv_factor(g00, inv_xn, atx);
    const float t1 = mv_factor(g11, inv_hn, ath);
    const float t2 = mv_factor(g22, inv_xn, atx);
    const float t3 = mv_factor(g33, inv_hn, ath);
    const float t4 = mv_factor(g44, inv_xn, atx);
    const float t5 = mv_factor(g55, inv_hn, ath);

    float cA, cB;
    madd_coef(t1 * g1z, t1 * t1 * g11, zz, cA, cB);
    const float u1 = cA * t1, u2 = cB;
    madd_coef(t0 * (u1 * g01 + u2 * g0z), t0 * t0 * g00,
              u1 * u1 * g11 + 2.f * u1 * u2 * g1z + u2 * u2 * zz, cA, cB);
    const float w0 = cA * t0, w1 = cB * u1, w2 = cB * u2;
    const float nz2 = w0 * w0 * g00 + w1 * w1 * g11 + w2 * w2 * zz +
                      2.f * (w0 * w1 * g01 + w0 * w2 * g0z + w1 * w2 * g1z);
    float inv_nz, nz;
    safe_norm(nz2, inv_nz, nz);
    const float fz = artanh_c(nz) * inv_nz;

    madd_coef(t3 * g3r, t3 * t3 * g33, rrb, cA, cB);
    const float v1 = cA * t3, v2 = cB;
    madd_coef(t2 * (v1 * g23 + v2 * g2r), t2 * t2 * g22,
              v1 * v1 * g33 + 2.f * v1 * v2 * g3r + v2 * v2 * rrb, cA, cB);
    const float y0 = cA * t2, y1 = cB * v1, y2 = cB * v2;
    const float nr2 = y0 * y0 * g22 + y1 * y1 * g33 + y2 * y2 * rrb +
                      2.f * (y0 * y1 * g23 + y0 * y2 * g2r + y1 * y2 * g3r);
    float inv_nr, nr;
    safe_norm(nr2, inv_nr, nr);
    const float fr = artanh_c(nr) * inv_nr;

    madd_coef(t5 * g5h, t5 * t5 * g55, bhbh, cA, cB);
    const float d5 = cA * t5, db = cB;
    const float ahh2 = d5 * d5 * g55 + 2.f * d5 * db * g5h + db * db * bhbh;

    if (tid == 0) {
        float* S = g_S + blockIdx.x * 16;
        S[0] = w0;  S[1] = w1;  S[2] = w2;  S[3] = fz;
        S[4] = y0;  S[5] = y1;  S[6] = y2;  S[7] = fr;
        S[8] = d5;  S[9] = db;  S[10] = t4; S[11] = ahh2;
        S[12] = hh; S[13] = g44; S[14] = g4H;
    }
}

// ----------------------------------------------------------------------------
// hyp_p2: Gram pass 2 -> output
// ----------------------------------------------------------------------------
__global__ void __launch_bounds__(256) hyp_p2(
    const float* __restrict__ prevh,
    const float* __restrict__ bzp, const float* __restrict__ brp,
    const float* __restrict__ bhp, float* __restrict__ out)
{
    __shared__ float buf[8 * 12];
    const int tid = threadIdx.x;
    const size_t off = (size_t)blockIdx.x * NDIM;
    const float* __restrict__ S = g_S + blockIdx.x * 16;

    const float w0 = S[0], w1 = S[1], w2 = S[2], fz = S[3];
    const float y0 = S[4], y1 = S[5], y2 = S[6], fr = S[7];
    const float d5 = S[8], db = S[9], t4 = S[10], ahh2 = S[11];
    const float hh = S[12], g44 = S[13], g4H = S[14];

    float z[VPT], q[VPT], H[VPT], G4[VPT];
    float s2[12];
#pragma unroll
    for (int i = 0; i < 12; i++) s2[i] = 0.f;

#pragma unroll
    for (int j = 0; j < VPT; j++) {
        const int c = j * RT + tid;
        const float g0 = __half2float(g_C[0 * GSZ + off + c]);
        const float g1 = __half2float(g_C[1 * GSZ + off + c]);
        z[j] = sigmoid_f(fz * (w0 * g0 + w1 * g1 + w2 * bzp[c]));
        const float g2 = __half2float(g_C[2 * GSZ + off + c]);
        const float g3 = __half2float(g_C[3 * GSZ + off + c]);
        const float rv = sigmoid_f(fr * (y0 * g2 + y1 * g3 + y2 * brp[c]));
        const float g5 = __half2float(g_C[5 * GSZ + off + c]);
        q[j] = rv * (d5 * g5 + db * bhp[c]);
        G4[j] = __half2float(g_C[4 * GSZ + off + c]);
        H[j]  = prevh[off + c];
        const float zh = z[j] * H[j], zq = z[j] * q[j], zg = z[j] * G4[j];
        s2[0]  = fmaf(q[j], q[j], s2[0]);
        s2[1]  = fmaf(q[j], G4[j], s2[1]);
        s2[2]  = fmaf(q[j], H[j], s2[2]);
        s2[3]  = fmaf(zh, zh, s2[3]);
        s2[4]  = fmaf(zh, zq, s2[4]);
        s2[5]  = fmaf(zh, zg, s2[5]);
        s2[6]  = fmaf(zq, zq, s2[6]);
        s2[7]  = fmaf(zq, zg, s2[7]);
        s2[8]  = fmaf(zg, zg, s2[8]);
        s2[9]  = fmaf(H[j], zh, s2[9]);
        s2[10] = fmaf(H[j], zq, s2[10]);
        s2[11] = fmaf(H[j], zg, s2[11]);
    }
    blockReduceN<12>(s2, buf);
    const float qq = s2[0], qg4 = s2[1], qh = s2[2];
    const float s11 = s2[3], s12 = s2[4], s13 = s2[5];
    const float s22 = s2[6], s23 = s2[7], s33 = s2[8];
    const float hzh = s2[9], hzq = s2[10], hzg4 = s2[11];

    float cA, cB;
    float inv_na, na, inv_nq, nq;
    safe_norm(ahh2, inv_na, na);
    safe_norm(qq, inv_nq, nq);
    const float tp = tanh_pos(nq * inv_na * artanh_c(na)) * inv_nq;

    madd_coef(tp * t4 * qg4, tp * tp * qq, t4 * t4 * g44, cA, cB);
    const float bq = cA * tp, b4 = cB * t4;

    const float temp2 = bq * bq * qq + 2.f * bq * b4 * qg4 + b4 * b4 * g44;
    madd_coef(-(bq * qh + b4 * g4H), hh, temp2, cA, cB);
    const float alpha = -cA, bq2 = cB * bq, b42 = cB * b4;

    const float mh2 = alpha * alpha * hh + bq2 * bq2 * qq + b42 * b42 * g44 +
                      2.f * (alpha * bq2 * qh + alpha * b42 * g4H + bq2 * b42 * qg4);
    const float ux2 = alpha * alpha * s11 + bq2 * bq2 * s22 + b42 * b42 * s33 +
                      2.f * (alpha * bq2 * s12 + alpha * b42 * s13 + bq2 * b42 * s23);
    float inv_nmh, nmh, inv_nux, nux;
    safe_norm(mh2, inv_nmh, nmh);
    safe_norm(ux2, inv_nux, nux);
    const float tz = tanh_pos(nux * inv_nmh * artanh_c(nmh)) * inv_nux;

    madd_coef(tz * (alpha * hzh + bq2 * hzq + b42 * hzg4), hh, tz * tz * ux2,
              cA, cB);
    const float k0 = cA;
    const float kz = cB * tz;
    const float ka = kz * alpha, kb = kz * bq2, kc = kz * b42;

#pragma unroll
    for (int j = 0; j < VPT; j++)
        out[off + j * RT + tid] =
            k0 * H[j] + z[j] * (ka * H[j] + kb * q[j] + kc * G4[j]);
}

// ----------------------------------------------------------------------------
// launch
// ----------------------------------------------------------------------------
extern "C" void kernel_launch(void* const* d_in, const int* in_sizes, int n_in,
                              void* d_out, int out_size)
{
    const float* inp   = (const float*)d_in[0];
    const float* prevh = (const float*)d_in[1];
    WPtrs wp;
    wp.w[0] = (const float*)d_in[2];  // w_inp_z
    wp.w[1] = (const float*)d_in[3];  // w_hid_z
    wp.w[2] = (const float*)d_in[5];  // w_inp_r
    wp.w[3] = (const float*)d_in[6];  // w_hid_r
    wp.w[4] = (const float*)d_in[8];  // w_inp_h
    wp.w[5] = (const float*)d_in[9];  // w_hid_h
    const float* b_z = (const float*)d_in[4];
    const float* b_r = (const float*)d_in[7];
    const float* b_h = (const float*)d_in[10];
    float* out = (float*)d_out;

    cudaFuncSetAttribute(gemm6, cudaFuncAttributeMaxDynamicSharedMemorySize,
                         SMEM_BYTES);

    split_act<<<8192, 256>>>(inp, prevh);
    split_wt<<<dim3(32, 32, 6), 256>>>(wp);
    gemm6<<<dim3(8, 32, 6), 256, SMEM_BYTES>>>();
    hyp_p1<<<MDIM, 256>>>(inp, prevh, b_z, b_r, b_h);
    hyp_p2<<<MDIM, 256>>>(prevh, b_z, b_r, b_h, out);
}

// round 15
// speedup vs baseline: 1.9593x; 1.0265x over previous
#include <cuda_runtime.h>
#include <cuda_bf16.h>
#include <cuda_fp16.h>
#include <cstdint>

// ============================================================================
// HyperGRUCell — round 15: vectorized hyp passes + fp16-C BK=64 gemm
//   split_act : fp32 -> fp16 for [inp; prev_h]
//   split_wt  : fp32 W[k][n] -> fp16 Wt[n][k]
//   gemm6     : C(fp16) = A@W^T (fp32 accum, HMMA, BK=64, 2-stage, 2 CTA/SM)
//   hyp_p1    : Gram pass 1 (wide loads) -> 15 scalars/row
//   hyp_p2    : Gram pass 2 (wide loads) -> output
// ============================================================================

#define MDIM 4096
#define NDIM 1024
#define KDIM 1024
#define GSZ  ((size_t)MDIM * NDIM)

__device__ __half g_C[6ull * MDIM * NDIM];      // fp16 C (48 MB)
__device__ __half g_Ah[8192ull * 1024];
__device__ __half g_Wh[6144ull * 1024];
__device__ float  g_S[4096 * 16];               // per-row pass-1 scalars

// ----------------------------------------------------------------------------
// split kernels (unchanged)
// ----------------------------------------------------------------------------
__global__ void __launch_bounds__(256) split_act(const float* __restrict__ inp,
                                                 const float* __restrict__ prevh)
{
    const size_t i = ((size_t)blockIdx.x * 256 + threadIdx.x) * 4;
    const size_t half = (size_t)MDIM * KDIM;
    const float* src = (i < half) ? (inp + i) : (prevh + (i - half));
    float4 v = *reinterpret_cast<const float4*>(src);
    float x[4] = {v.x, v.y, v.z, v.w};
    uint32_t hp[2];
#pragma unroll
    for (int j = 0; j < 2; j++) {
        __half h0 = __float2half_rn(x[2 * j]);
        __half h1 = __float2half_rn(x[2 * j + 1]);
        hp[j] = (uint32_t)__half_as_ushort(h0) |
                ((uint32_t)__half_as_ushort(h1) << 16);
    }
    *reinterpret_cast<uint2*>(reinterpret_cast<char*>(g_Ah) + i * 2) = make_uint2(hp[0], hp[1]);
}

struct WPtrs { const float* w[6]; };

__global__ void __launch_bounds__(256) split_wt(WPtrs wp)
{
    __shared__ float t[32][33];
    const int g = blockIdx.z;
    const float* __restrict__ W = wp.w[g];
    const int tx = threadIdx.x & 31, ty = threadIdx.x >> 5;
    const int n0 = blockIdx.x * 32, k0 = blockIdx.y * 32;
#pragma unroll
    for (int j = 0; j < 4; j++)
        t[ty + j * 8][tx] = W[(size_t)(k0 + ty + j * 8) * NDIM + n0 + tx];
    __syncthreads();
#pragma unroll
    for (int j = 0; j < 4; j++) {
        const float v = t[tx][ty + j * 8];
        const size_t o = (size_t)(g * 1024 + n0 + ty + j * 8) * KDIM + k0 + tx;
        g_Wh[o] = __float2half_rn(v);
    }
}

// ----------------------------------------------------------------------------
// gemm6 (unchanged from round 14)
// ----------------------------------------------------------------------------
#define SSTRIDE 72
#define MAT_ELEMS (128 * SSTRIDE)
#define STAGE_ELEMS (2 * MAT_ELEMS)
#define NSTAGE 2
#define SMEM_BYTES (NSTAGE * STAGE_ELEMS * 2)

__device__ __forceinline__ void cp16(uint32_t dst, const void* src)
{
    asm volatile("cp.async.cg.shared.global [%0], [%1], 16;"
                 :: "r"(dst), "l"(src) : "memory");
}
#define CP_COMMIT() asm volatile("cp.async.commit_group;" ::: "memory")
#define CP_WAIT(n)  asm volatile("cp.async.wait_group %0;" :: "n"(n) : "memory")

__device__ __forceinline__ void ldsm4(uint32_t* d, uint32_t addr)
{
    asm volatile("ldmatrix.sync.aligned.m8n8.x4.shared.b16 {%0,%1,%2,%3}, [%4];"
                 : "=r"(d[0]), "=r"(d[1]), "=r"(d[2]), "=r"(d[3]) : "r"(addr));
}

__device__ __forceinline__ void mma16816(float* c, const uint32_t* a,
                                         const uint32_t* b)
{
    asm volatile(
        "mma.sync.aligned.m16n8k16.row.col.f32.f16.f16.f32 "
        "{%0,%1,%2,%3}, {%4,%5,%6,%7}, {%8,%9}, {%0,%1,%2,%3};"
        : "+f"(c[0]), "+f"(c[1]), "+f"(c[2]), "+f"(c[3])
        : "r"(a[0]), "r"(a[1]), "r"(a[2]), "r"(a[3]), "r"(b[0]), "r"(b[1]));
}

__global__ void __launch_bounds__(256, 2) gemm6()
{
    extern __shared__ __half smem[];
    uint32_t sb;
    asm("{ .reg .u64 t; cvta.to.shared.u64 t, %1; cvt.u32.u64 %0, t; }"
        : "=r"(sb) : "l"(smem));

    const int tid  = threadIdx.x;
    const int lane = tid & 31, wid = tid >> 5;
    const int wm = wid >> 2, wn = wid & 3;

    const int g  = blockIdx.z;
    const int bm = blockIdx.y * 128;
    const int bn = blockIdx.x * 128;
    const int arow = ((g & 1) << 12) + bm;
    const int wrow = (g << 10) + bn;

    const __half* gb[2] = {
        g_Ah + (size_t)arow * KDIM, g_Wh + (size_t)wrow * KDIM};

    int l_mat[8], l_row[8], l_ch[8];
#pragma unroll
    for (int i = 0; i < 8; i++) {
        const int idx = tid + i * 256;
        l_mat[i] = idx >> 10;
        const int wi = idx & 1023;
        l_row[i] = wi >> 3;
        l_ch[i]  = wi & 7;
    }

#define LOAD_STAGE(kt, s)                                                      \
    do {                                                                       \
        const uint32_t sbase_ = sb + (uint32_t)(s) * (STAGE_ELEMS * 2);        \
        _Pragma("unroll")                                                      \
        for (int i = 0; i < 8; i++) {                                          \
            const uint32_t dst = sbase_ +                                      \
                (uint32_t)(l_mat[i] * MAT_ELEMS + l_row[i] * SSTRIDE +         \
                           l_ch[i] * 8) * 2;                                   \
            cp16(dst, gb[l_mat[i]] + (size_t)l_row[i] * KDIM +                 \
                      (kt) * 64 + l_ch[i] * 8);                                \
        }                                                                      \
    } while (0)

    float acc[4][4][4];
#pragma unroll
    for (int mt = 0; mt < 4; mt++)
#pragma unroll
        for (int nt = 0; nt < 4; nt++)
#pragma unroll
            for (int j = 0; j < 4; j++) acc[mt][nt][j] = 0.f;

    LOAD_STAGE(0, 0); CP_COMMIT();
    LOAD_STAGE(1, 1); CP_COMMIT();

    const int a_r = (lane & 7) + ((lane >> 3) & 1) * 8;
    const int a_c = (lane >> 4) * 8;
    const int b_r = (lane & 7) + (lane >> 4) * 8;
    const int b_c = ((lane >> 3) & 1) * 8;

    for (int kt = 0; kt < 16; kt++) {
        CP_WAIT(1);
        __syncthreads();

        const uint32_t sbase = sb + (uint32_t)(kt & 1) * (STAGE_ELEMS * 2);
#pragma unroll
        for (int ks = 0; ks < 4; ks++) {
            uint32_t a[4][4], bq[4][2];
#pragma unroll
            for (int p = 0; p < 2; p++) {
                uint32_t q[4];
                ldsm4(q, sbase + (uint32_t)(MAT_ELEMS +
                        (wn * 32 + p * 16 + b_r) * SSTRIDE + ks * 16 + b_c) * 2);
                bq[2 * p][0] = q[0]; bq[2 * p][1] = q[1];
                bq[2 * p + 1][0] = q[2]; bq[2 * p + 1][1] = q[3];
            }
#pragma unroll
            for (int mt = 0; mt < 4; mt++)
                ldsm4(a[mt], sbase +
                      (uint32_t)((wm * 64 + mt * 16 + a_r) * SSTRIDE +
                                 ks * 16 + a_c) * 2);
#pragma unroll
            for (int mt = 0; mt < 4; mt++)
#pragma unroll
                for (int nt = 0; nt < 4; nt++)
                    mma16816(acc[mt][nt], a[mt], bq[nt]);
        }

        __syncthreads();
        if (kt + 2 < 16) LOAD_STAGE(kt + 2, kt & 1);
        CP_COMMIT();
    }
    CP_WAIT(0);

    __half* Cb = g_C + (size_t)g * GSZ;
    const int mrow = bm + wm * 64 + (lane >> 2);
    const int ncol = bn + wn * 32 + (lane & 3) * 2;
#pragma unroll
    for (int mt = 0; mt < 4; mt++) {
#pragma unroll
        for (int nt = 0; nt < 4; nt++) {
            __half* p0 = Cb + (size_t)(mrow + mt * 16) * NDIM + ncol + nt * 8;
            *reinterpret_cast<__half2*>(p0) =
                __floats2half2_rn(acc[mt][nt][0], acc[mt][nt][1]);
            *reinterpret_cast<__half2*>(p0 + 8 * NDIM) =
                __floats2half2_rn(acc[mt][nt][2], acc[mt][nt][3]);
        }
    }
#undef LOAD_STAGE
}

// ----------------------------------------------------------------------------
// hyperbolic math helpers
// ----------------------------------------------------------------------------
#define VPT 4

__device__ __forceinline__ float artanh_c(float x)
{
    x = fminf(fmaxf(x, -1.f + 1e-5f), 1.f - 1e-5f);
    return 0.5f * __logf(__fdividef(1.f + x, 1.f - x));
}

__device__ __forceinline__ float tanh_pos(float v)   // v >= 0
{
    return 1.f - __fdividef(2.f, __expf(2.f * v) + 1.f);
}

__device__ __forceinline__ float sigmoid_f(float v)
{
    return __fdividef(1.f, 1.f + __expf(-v));
}

__device__ __forceinline__ void safe_norm(float v2, float& inv_n, float& n)
{
    const float vc = fmaxf(v2, 1e-15f);
    inv_n = rsqrtf(vc);
    n = vc * inv_n;
}

__device__ __forceinline__ float mv_factor(float g2, float inv_xn, float atx)
{
    float inv_gn, gn;
    safe_norm(g2, inv_gn, gn);
    return tanh_pos(gn * inv_xn * atx) * inv_gn;
}

__device__ __forceinline__ void madd_coef(float ab, float a2, float b2,
                                          float& cA, float& cB)
{
    const float inv = __fdividef(1.f, 1.f + 2.f * ab + a2 * b2);
    cA = (1.f + 2.f * ab + b2) * inv;
    cB = (1.f - a2) * inv;
}

// 8-byte load of 4 halfs -> 4 floats
__device__ __forceinline__ void ld4h(const __half* p, float* o)
{
    const uint2 u = *reinterpret_cast<const uint2*>(p);
    const __half2 a = *reinterpret_cast<const __half2*>(&u.x);
    const __half2 b = *reinterpret_cast<const __half2*>(&u.y);
    const float2 fa = __half22float2(a);
    const float2 fb = __half22float2(b);
    o[0] = fa.x; o[1] = fa.y; o[2] = fb.x; o[3] = fb.y;
}

__device__ __forceinline__ void ld4f(const float* p, float* o)
{
    const float4 v = *reinterpret_cast<const float4*>(p);
    o[0] = v.x; o[1] = v.y; o[2] = v.z; o[3] = v.w;
}

template <int N>
__device__ __forceinline__ void blockReduceN(float* v, float* buf)
{
    const int lane = threadIdx.x & 31, wid = threadIdx.x >> 5;
#pragma unroll
    for (int o = 16; o; o >>= 1)
#pragma unroll
        for (int i = 0; i < N; i++)
            v[i] += __shfl_xor_sync(0xffffffffu, v[i], o);
    if (lane == 0)
#pragma unroll
        for (int i = 0; i < N; i++) buf[wid * N + i] = v[i];
    __syncthreads();
#pragma unroll
    for (int i = 0; i < N; i++) {
        float s = 0.f;
#pragma unroll
        for (int w = 0; w < 8; w++) s += buf[w * N + i];
        v[i] = s;
    }
}

// ----------------------------------------------------------------------------
// hyp_p1: Gram pass 1 (wide loads) -> 15 scalars per row
// ----------------------------------------------------------------------------
__global__ void __launch_bounds__(256) hyp_p1(
    const float* __restrict__ inp, const float* __restrict__ prevh,
    const float* __restrict__ bzp, const float* __restrict__ brp,
    const float* __restrict__ bhp)
{
    __shared__ float buf[8 * 19];
    const int tid = threadIdx.x;
    const size_t off = (size_t)blockIdx.x * NDIM;
    const int c = tid * 4;

    float s[19];
#pragma unroll
    for (int i = 0; i < 19; i++) s[i] = 0.f;

    float X[4], H[4], u[4], v[4], b[4];

    // x, H
    ld4f(inp + off + c, X);
    ld4f(prevh + off + c, H);
#pragma unroll
    for (int j = 0; j < 4; j++) {
        s[0] = fmaf(X[j], X[j], s[0]);
        s[1] = fmaf(H[j], H[j], s[1]);
    }
    // G0, G1, BZ
    ld4h(g_C + 0 * GSZ + off + c, u);
    ld4h(g_C + 1 * GSZ + off + c, v);
    ld4f(bzp + c, b);
#pragma unroll
    for (int j = 0; j < 4; j++) {
        s[2] = fmaf(u[j], u[j], s[2]);
        s[3] = fmaf(v[j], v[j], s[3]);
        s[4] = fmaf(u[j], v[j], s[4]);
        s[5] = fmaf(u[j], b[j], s[5]);
        s[6] = fmaf(v[j], b[j], s[6]);
        s[7] = fmaf(b[j], b[j], s[7]);
    }
    // G2, G3, BR
    ld4h(g_C + 2 * GSZ + off + c, u);
    ld4h(g_C + 3 * GSZ + off + c, v);
    ld4f(brp + c, b);
#pragma unroll
    for (int j = 0; j < 4; j++) {
        s[8]  = fmaf(u[j], u[j], s[8]);
        s[9]  = fmaf(v[j], v[j], s[9]);
        s[10] = fmaf(u[j], v[j], s[10]);
        s[11] = fmaf(u[j], b[j], s[11]);
        s[12] = fmaf(v[j], b[j], s[12]);
        s[13] = fmaf(b[j], b[j], s[13]);
    }
    // G5, BH
    ld4h(g_C + 5 * GSZ + off + c, u);
    ld4f(bhp + c, b);
#pragma unroll
    for (int j = 0; j < 4; j++) {
        s[14] = fmaf(u[j], u[j], s[14]);
        s[15] = fmaf(u[j], b[j], s[15]);
        s[16] = fmaf(b[j], b[j], s[16]);
    }
    // G4 (with H)
    ld4h(g_C + 4 * GSZ + off + c, u);
#pragma unroll
    for (int j = 0; j < 4; j++) {
        s[17] = fmaf(u[j], u[j], s[17]);
        s[18] = fmaf(u[j], H[j], s[18]);
    }

    blockReduceN<19>(s, buf);
    if (tid >= 32) return;

    const float xx = s[0], hh = s[1];
    const float g00 = s[2], g11 = s[3], g01 = s[4], g0z = s[5], g1z = s[6], zz = s[7];
    const float g22 = s[8], g33 = s[9], g23 = s[10], g2r = s[11], g3r = s[12], rrb = s[13];
    const float g55 = s[14], g5h = s[15], bhbh = s[16], g44 = s[17], g4H = s[18];

    float inv_xn, xn, inv_hn, hn;
    safe_norm(xx, inv_xn, xn);
    safe_norm(hh, inv_hn, hn);
    const float atx = artanh_c(xn);
    const float ath = artanh_c(hn);

    const float t0 = mv_factor(g00, inv_xn, atx);
    const float t1 = mv_factor(g11, inv_hn, ath);
    const float t2 = mv_factor(g22, inv_xn, atx);
    const float t3 = mv_factor(g33, inv_hn, ath);
    const float t4 = mv_factor(g44, inv_xn, atx);
    const float t5 = mv_factor(g55, inv_hn, ath);

    float cA, cB;
    madd_coef(t1 * g1z, t1 * t1 * g11, zz, cA, cB);
    const float u1 = cA * t1, u2 = cB;
    madd_coef(t0 * (u1 * g01 + u2 * g0z), t0 * t0 * g00,
              u1 * u1 * g11 + 2.f * u1 * u2 * g1z + u2 * u2 * zz, cA, cB);
    const float w0 = cA * t0, w1 = cB * u1, w2 = cB * u2;
    const float nz2 = w0 * w0 * g00 + w1 * w1 * g11 + w2 * w2 * zz +
                      2.f * (w0 * w1 * g01 + w0 * w2 * g0z + w1 * w2 * g1z);
    float inv_nz, nz;
    safe_norm(nz2, inv_nz, nz);
    const float fz = artanh_c(nz) * inv_nz;

    madd_coef(t3 * g3r, t3 * t3 * g33, rrb, cA, cB);
    const float v1 = cA * t3, v2 = cB;
    madd_coef(t2 * (v1 * g23 + v2 * g2r), t2 * t2 * g22,
              v1 * v1 * g33 + 2.f * v1 * v2 * g3r + v2 * v2 * rrb, cA, cB);
    const float y0 = cA * t2, y1 = cB * v1, y2 = cB * v2;
    const float nr2 = y0 * y0 * g22 + y1 * y1 * g33 + y2 * y2 * rrb +
                      2.f * (y0 * y1 * g23 + y0 * y2 * g2r + y1 * y2 * g3r);
    float inv_nr, nr;
    safe_norm(nr2, inv_nr, nr);
    const float fr = artanh_c(nr) * inv_nr;

    madd_coef(t5 * g5h, t5 * t5 * g55, bhbh, cA, cB);
    const float d5 = cA * t5, db = cB;
    const float ahh2 = d5 * d5 * g55 + 2.f * d5 * db * g5h + db * db * bhbh;

    if (tid == 0) {
        float* S = g_S + blockIdx.x * 16;
        S[0] = w0;  S[1] = w1;  S[2] = w2;  S[3] = fz;
        S[4] = y0;  S[5] = y1;  S[6] = y2;  S[7] = fr;
        S[8] = d5;  S[9] = db;  S[10] = t4; S[11] = ahh2;
        S[12] = hh; S[13] = g44; S[14] = g4H;
    }
}

// ----------------------------------------------------------------------------
// hyp_p2: Gram pass 2 (wide loads) -> output
// ----------------------------------------------------------------------------
__global__ void __launch_bounds__(256) hyp_p2(
    const float* __restrict__ prevh,
    const float* __restrict__ bzp, const float* __restrict__ brp,
    const float* __restrict__ bhp, float* __restrict__ out)
{
    __shared__ float buf[8 * 12];
    const int tid = threadIdx.x;
    const size_t off = (size_t)blockIdx.x * NDIM;
    const int c = tid * 4;
    const float* __restrict__ S = g_S + blockIdx.x * 16;

    const float w0 = S[0], w1 = S[1], w2 = S[2], fz = S[3];
    const float y0 = S[4], y1 = S[5], y2 = S[6], fr = S[7];
    const float d5 = S[8], db = S[9], t4 = S[10], ahh2 = S[11];
    const float hh = S[12], g44 = S[13], g4H = S[14];

    float z[4], q[4], H[4], G4[4];
    float ua[4], ub[4], bb[4];
    float s2[12];
#pragma unroll
    for (int i = 0; i < 12; i++) s2[i] = 0.f;

    // z
    ld4h(g_C + 0 * GSZ + off + c, ua);
    ld4h(g_C + 1 * GSZ + off + c, ub);
    ld4f(bzp + c, bb);
#pragma unroll
    for (int j = 0; j < 4; j++)
        z[j] = sigmoid_f(fz * (w0 * ua[j] + w1 * ub[j] + w2 * bb[j]));
    // r -> q
    ld4h(g_C + 2 * GSZ + off + c, ua);
    ld4h(g_C + 3 * GSZ + off + c, ub);
    ld4f(brp + c, bb);
#pragma unroll
    for (int j = 0; j < 4; j++)
        q[j] = sigmoid_f(fr * (y0 * ua[j] + y1 * ub[j] + y2 * bb[j]));
    ld4h(g_C + 5 * GSZ + off + c, ua);
    ld4f(bhp + c, bb);
#pragma unroll
    for (int j = 0; j < 4; j++)
        q[j] *= (d5 * ua[j] + db * bb[j]);

    ld4h(g_C + 4 * GSZ + off + c, G4);
    ld4f(prevh + off + c, H);

#pragma unroll
    for (int j = 0; j < 4; j++) {
        const float zh = z[j] * H[j], zq = z[j] * q[j], zg = z[j] * G4[j];
        s2[0]  = fmaf(q[j], q[j], s2[0]);
        s2[1]  = fmaf(q[j], G4[j], s2[1]);
        s2[2]  = fmaf(q[j], H[j], s2[2]);
        s2[3]  = fmaf(zh, zh, s2[3]);
        s2[4]  = fmaf(zh, zq, s2[4]);
        s2[5]  = fmaf(zh, zg, s2[5]);
        s2[6]  = fmaf(zq, zq, s2[6]);
        s2[7]  = fmaf(zq, zg, s2[7]);
        s2[8]  = fmaf(zg, zg, s2[8]);
        s2[9]  = fmaf(H[j], zh, s2[9]);
        s2[10] = fmaf(H[j], zq, s2[10]);
        s2[11] = fmaf(H[j], zg, s2[11]);
    }
    blockReduceN<12>(s2, buf);
    const float qq = s2[0], qg4 = s2[1], qh = s2[2];
    const float s11 = s2[3], s12 = s2[4], s13 = s2[5];
    const float s22 = s2[6], s23 = s2[7], s33 = s2[8];
    const float hzh = s2[9], hzq = s2[10], hzg4 = s2[11];

    float cA, cB;
    float inv_na, na, inv_nq, nq;
    safe_norm(ahh2, inv_na, na);
    safe_norm(qq, inv_nq, nq);
    const float tp = tanh_pos(nq * inv_na * artanh_c(na)) * inv_nq;

    madd_coef(tp * t4 * qg4, tp * tp * qq, t4 * t4 * g44, cA, cB);
    const float bq = cA * tp, b4 = cB * t4;

    const float temp2 = bq * bq * qq + 2.f * bq * b4 * qg4 + b4 * b4 * g44;
    madd_coef(-(bq * qh + b4 * g4H), hh, temp2, cA, cB);
    const float alpha = -cA, bq2 = cB * bq, b42 = cB * b4;

    const float mh2 = alpha * alpha * hh + bq2 * bq2 * qq + b42 * b42 * g44 +
                      2.f * (alpha * bq2 * qh + alpha * b42 * g4H + bq2 * b42 * qg4);
    const float ux2 = alpha * alpha * s11 + bq2 * bq2 * s22 + b42 * b42 * s33 +
                      2.f * (alpha * bq2 * s12 + alpha * b42 * s13 + bq2 * b42 * s23);
    float inv_nmh, nmh, inv_nux, nux;
    safe_norm(mh2, inv_nmh, nmh);
    safe_norm(ux2, inv_nux, nux);
    const float tz = tanh_pos(nux * inv_nmh * artanh_c(nmh)) * inv_nux;

    madd_coef(tz * (alpha * hzh + bq2 * hzq + b42 * hzg4), hh, tz * tz * ux2,
              cA, cB);
    const float k0 = cA;
    const float kz = cB * tz;
    const float ka = kz * alpha, kb = kz * bq2, kc = kz * b42;

    float4 o;
    o.x = k0 * H[0] + z[0] * (ka * H[0] + kb * q[0] + kc * G4[0]);
    o.y = k0 * H[1] + z[1] * (ka * H[1] + kb * q[1] + kc * G4[1]);
    o.z = k0 * H[2] + z[2] * (ka * H[2] + kb * q[2] + kc * G4[2]);
    o.w = k0 * H[3] + z[3] * (ka * H[3] + kb * q[3] + kc * G4[3]);
    *reinterpret_cast<float4*>(out + off + c) = o;
}

// ----------------------------------------------------------------------------
// launch
// ----------------------------------------------------------------------------
extern "C" void kernel_launch(void* const* d_in, const int* in_sizes, int n_in,
                              void* d_out, int out_size)
{
    const float* inp   = (const float*)d_in[0];
    const float* prevh = (const float*)d_in[1];
    WPtrs wp;
    wp.w[0] = (const float*)d_in[2];  // w_inp_z
    wp.w[1] = (const float*)d_in[3];  // w_hid_z
    wp.w[2] = (const float*)d_in[5];  // w_inp_r
    wp.w[3] = (const float*)d_in[6];  // w_hid_r
    wp.w[4] = (const float*)d_in[8];  // w_inp_h
    wp.w[5] = (const float*)d_in[9];  // w_hid_h
    const float* b_z = (const float*)d_in[4];
    const float* b_r = (const float*)d_in[7];
    const float* b_h = (const float*)d_in[10];
    float* out = (float*)d_out;

    cudaFuncSetAttribute(gemm6, cudaFuncAttributeMaxDynamicSharedMemorySize,
                         SMEM_BYTES);

    split_act<<<8192, 256>>>(inp, prevh);
    split_wt<<<dim3(32, 32, 6), 256>>>(wp);
    gemm6<<<dim3(8, 32, 6), 256, SMEM_BYTES>>>();
    hyp_p1<<<MDIM, 256>>>(inp, prevh, b_z, b_r, b_h);
    hyp_p2<<<MDIM, 256>>>(prevh, b_z, b_r, b_h, out);
}

// round 16
// speedup vs baseline: 2.0606x; 1.0517x over previous
#include <cuda_runtime.h>
#include <cuda_bf16.h>
#include <cuda_fp16.h>
#include <cstdint>

// ============================================================================
// HyperGRUCell — round 16: VPT=8 hyp passes + 3-stage BK=64 fp16-C gemm
//   split_act : fp32 -> fp16 for [inp; prev_h]
//   split_wt  : fp32 W[k][n] -> fp16 Wt[n][k]
//   gemm6     : C(fp16) = A@W^T (fp32 accum, HMMA, BK=64, 3-stage, 2 CTA/SM)
//   hyp_p1    : Gram pass 1 (16B loads, VPT=8, 128 thr) -> 15 scalars/row
//   hyp_p2    : Gram pass 2 (16B loads, VPT=8, 128 thr) -> output
// ============================================================================

#define MDIM 4096
#define NDIM 1024
#define KDIM 1024
#define GSZ  ((size_t)MDIM * NDIM)

__device__ __half g_C[6ull * MDIM * NDIM];      // fp16 C (48 MB)
__device__ __half g_Ah[8192ull * 1024];
__device__ __half g_Wh[6144ull * 1024];
__device__ float  g_S[4096 * 16];               // per-row pass-1 scalars

// ----------------------------------------------------------------------------
// split kernels (unchanged)
// ----------------------------------------------------------------------------
__global__ void __launch_bounds__(256) split_act(const float* __restrict__ inp,
                                                 const float* __restrict__ prevh)
{
    const size_t i = ((size_t)blockIdx.x * 256 + threadIdx.x) * 4;
    const size_t half = (size_t)MDIM * KDIM;
    const float* src = (i < half) ? (inp + i) : (prevh + (i - half));
    float4 v = *reinterpret_cast<const float4*>(src);
    float x[4] = {v.x, v.y, v.z, v.w};
    uint32_t hp[2];
#pragma unroll
    for (int j = 0; j < 2; j++) {
        __half h0 = __float2half_rn(x[2 * j]);
        __half h1 = __float2half_rn(x[2 * j + 1]);
        hp[j] = (uint32_t)__half_as_ushort(h0) |
                ((uint32_t)__half_as_ushort(h1) << 16);
    }
    *reinterpret_cast<uint2*>(reinterpret_cast<char*>(g_Ah) + i * 2) = make_uint2(hp[0], hp[1]);
}

struct WPtrs { const float* w[6]; };

__global__ void __launch_bounds__(256) split_wt(WPtrs wp)
{
    __shared__ float t[32][33];
    const int g = blockIdx.z;
    const float* __restrict__ W = wp.w[g];
    const int tx = threadIdx.x & 31, ty = threadIdx.x >> 5;
    const int n0 = blockIdx.x * 32, k0 = blockIdx.y * 32;
#pragma unroll
    for (int j = 0; j < 4; j++)
        t[ty + j * 8][tx] = W[(size_t)(k0 + ty + j * 8) * NDIM + n0 + tx];
    __syncthreads();
#pragma unroll
    for (int j = 0; j < 4; j++) {
        const float v = t[tx][ty + j * 8];
        const size_t o = (size_t)(g * 1024 + n0 + ty + j * 8) * KDIM + k0 + tx;
        g_Wh[o] = __float2half_rn(v);
    }
}

// ----------------------------------------------------------------------------
// gemm6: BM=BN=128, BK=64, 3 stages, 2 CTAs/SM, single product, fp16 out
// ----------------------------------------------------------------------------
#define SSTRIDE 72
#define MAT_ELEMS (128 * SSTRIDE)
#define STAGE_ELEMS (2 * MAT_ELEMS)
#define NSTAGE 3
#define SMEM_BYTES (NSTAGE * STAGE_ELEMS * 2)   // 110592

__device__ __forceinline__ void cp16(uint32_t dst, const void* src)
{
    asm volatile("cp.async.cg.shared.global [%0], [%1], 16;"
                 :: "r"(dst), "l"(src) : "memory");
}
#define CP_COMMIT() asm volatile("cp.async.commit_group;" ::: "memory")
#define CP_WAIT(n)  asm volatile("cp.async.wait_group %0;" :: "n"(n) : "memory")

__device__ __forceinline__ void ldsm4(uint32_t* d, uint32_t addr)
{
    asm volatile("ldmatrix.sync.aligned.m8n8.x4.shared.b16 {%0,%1,%2,%3}, [%4];"
                 : "=r"(d[0]), "=r"(d[1]), "=r"(d[2]), "=r"(d[3]) : "r"(addr));
}

__device__ __forceinline__ void mma16816(float* c, const uint32_t* a,
                                         const uint32_t* b)
{
    asm volatile(
        "mma.sync.aligned.m16n8k16.row.col.f32.f16.f16.f32 "
        "{%0,%1,%2,%3}, {%4,%5,%6,%7}, {%8,%9}, {%0,%1,%2,%3};"
        : "+f"(c[0]), "+f"(c[1]), "+f"(c[2]), "+f"(c[3])
        : "r"(a[0]), "r"(a[1]), "r"(a[2]), "r"(a[3]), "r"(b[0]), "r"(b[1]));
}

__global__ void __launch_bounds__(256, 2) gemm6()
{
    extern __shared__ __half smem[];
    uint32_t sb;
    asm("{ .reg .u64 t; cvta.to.shared.u64 t, %1; cvt.u32.u64 %0, t; }"
        : "=r"(sb) : "l"(smem));

    const int tid  = threadIdx.x;
    const int lane = tid & 31, wid = tid >> 5;
    const int wm = wid >> 2, wn = wid & 3;

    const int g  = blockIdx.z;
    const int bm = blockIdx.y * 128;
    const int bn = blockIdx.x * 128;
    const int arow = ((g & 1) << 12) + bm;
    const int wrow = (g << 10) + bn;

    const __half* gb[2] = {
        g_Ah + (size_t)arow * KDIM, g_Wh + (size_t)wrow * KDIM};

    int l_mat[8], l_row[8], l_ch[8];
#pragma unroll
    for (int i = 0; i < 8; i++) {
        const int idx = tid + i * 256;
        l_mat[i] = idx >> 10;
        const int wi = idx & 1023;
        l_row[i] = wi >> 3;
        l_ch[i]  = wi & 7;
    }

#define LOAD_STAGE(kt, s)                                                      \
    do {                                                                       \
        const uint32_t sbase_ = sb + (uint32_t)(s) * (STAGE_ELEMS * 2);        \
        _Pragma("unroll")                                                      \
        for (int i = 0; i < 8; i++) {                                          \
            const uint32_t dst = sbase_ +                                      \
                (uint32_t)(l_mat[i] * MAT_ELEMS + l_row[i] * SSTRIDE +         \
                           l_ch[i] * 8) * 2;                                   \
            cp16(dst, gb[l_mat[i]] + (size_t)l_row[i] * KDIM +                 \
                      (kt) * 64 + l_ch[i] * 8);                                \
        }                                                                      \
    } while (0)

    float acc[4][4][4];
#pragma unroll
    for (int mt = 0; mt < 4; mt++)
#pragma unroll
        for (int nt = 0; nt < 4; nt++)
#pragma unroll
            for (int j = 0; j < 4; j++) acc[mt][nt][j] = 0.f;

    LOAD_STAGE(0, 0); CP_COMMIT();
    LOAD_STAGE(1, 1); CP_COMMIT();
    LOAD_STAGE(2, 2); CP_COMMIT();

    const int a_r = (lane & 7) + ((lane >> 3) & 1) * 8;
    const int a_c = (lane >> 4) * 8;
    const int b_r = (lane & 7) + (lane >> 4) * 8;
    const int b_c = ((lane >> 3) & 1) * 8;

    for (int kt = 0; kt < 16; kt++) {
        CP_WAIT(2);
        __syncthreads();

        const int slot = kt % 3;
        const uint32_t sbase = sb + (uint32_t)slot * (STAGE_ELEMS * 2);
#pragma unroll
        for (int ks = 0; ks < 4; ks++) {
            uint32_t a[4][4], bq[4][2];
#pragma unroll
            for (int p = 0; p < 2; p++) {
                uint32_t q[4];
                ldsm4(q, sbase + (uint32_t)(MAT_ELEMS +
                        (wn * 32 + p * 16 + b_r) * SSTRIDE + ks * 16 + b_c) * 2);
                bq[2 * p][0] = q[0]; bq[2 * p][1] = q[1];
                bq[2 * p + 1][0] = q[2]; bq[2 * p + 1][1] = q[3];
            }
#pragma unroll
            for (int mt = 0; mt < 4; mt++)
                ldsm4(a[mt], sbase +
                      (uint32_t)((wm * 64 + mt * 16 + a_r) * SSTRIDE +
                                 ks * 16 + a_c) * 2);
#pragma unroll
            for (int mt = 0; mt < 4; mt++)
#pragma unroll
                for (int nt = 0; nt < 4; nt++)
                    mma16816(acc[mt][nt], a[mt], bq[nt]);
        }

        __syncthreads();
        if (kt + 3 < 16) LOAD_STAGE(kt + 3, slot);
        CP_COMMIT();
    }
    CP_WAIT(0);

    __half* Cb = g_C + (size_t)g * GSZ;
    const int mrow = bm + wm * 64 + (lane >> 2);
    const int ncol = bn + wn * 32 + (lane & 3) * 2;
#pragma unroll
    for (int mt = 0; mt < 4; mt++) {
#pragma unroll
        for (int nt = 0; nt < 4; nt++) {
            __half* p0 = Cb + (size_t)(mrow + mt * 16) * NDIM + ncol + nt * 8;
            *reinterpret_cast<__half2*>(p0) =
                __floats2half2_rn(acc[mt][nt][0], acc[mt][nt][1]);
            *reinterpret_cast<__half2*>(p0 + 8 * NDIM) =
                __floats2half2_rn(acc[mt][nt][2], acc[mt][nt][3]);
        }
    }
#undef LOAD_STAGE
}

// ----------------------------------------------------------------------------
// hyperbolic math helpers
// ----------------------------------------------------------------------------
__device__ __forceinline__ float artanh_c(float x)
{
    x = fminf(fmaxf(x, -1.f + 1e-5f), 1.f - 1e-5f);
    return 0.5f * __logf(__fdividef(1.f + x, 1.f - x));
}

__device__ __forceinline__ float tanh_pos(float v)   // v >= 0
{
    return 1.f - __fdividef(2.f, __expf(2.f * v) + 1.f);
}

__device__ __forceinline__ float sigmoid_f(float v)
{
    return __fdividef(1.f, 1.f + __expf(-v));
}

__device__ __forceinline__ void safe_norm(float v2, float& inv_n, float& n)
{
    const float vc = fmaxf(v2, 1e-15f);
    inv_n = rsqrtf(vc);
    n = vc * inv_n;
}

__device__ __forceinline__ float mv_factor(float g2, float inv_xn, float atx)
{
    float inv_gn, gn;
    safe_norm(g2, inv_gn, gn);
    return tanh_pos(gn * inv_xn * atx) * inv_gn;
}

__device__ __forceinline__ void madd_coef(float ab, float a2, float b2,
                                          float& cA, float& cB)
{
    const float inv = __fdividef(1.f, 1.f + 2.f * ab + a2 * b2);
    cA = (1.f + 2.f * ab + b2) * inv;
    cB = (1.f - a2) * inv;
}

// 16-byte load of 8 halfs -> 8 floats
__device__ __forceinline__ void ld8h(const __half* p, float* o)
{
    const uint4 u = *reinterpret_cast<const uint4*>(p);
    const float2 f0 = __half22float2(*reinterpret_cast<const __half2*>(&u.x));
    const float2 f1 = __half22float2(*reinterpret_cast<const __half2*>(&u.y));
    const float2 f2 = __half22float2(*reinterpret_cast<const __half2*>(&u.z));
    const float2 f3 = __half22float2(*reinterpret_cast<const __half2*>(&u.w));
    o[0] = f0.x; o[1] = f0.y; o[2] = f1.x; o[3] = f1.y;
    o[4] = f2.x; o[5] = f2.y; o[6] = f3.x; o[7] = f3.y;
}

// two float4 loads -> 8 floats
__device__ __forceinline__ void ld8f(const float* p, float* o)
{
    const float4 a = *reinterpret_cast<const float4*>(p);
    const float4 b = *reinterpret_cast<const float4*>(p + 4);
    o[0] = a.x; o[1] = a.y; o[2] = a.z; o[3] = a.w;
    o[4] = b.x; o[5] = b.y; o[6] = b.z; o[7] = b.w;
}

template <int N, int NW>
__device__ __forceinline__ void blockReduceN(float* v, float* buf)
{
    const int lane = threadIdx.x & 31, wid = threadIdx.x >> 5;
#pragma unroll
    for (int o = 16; o; o >>= 1)
#pragma unroll
        for (int i = 0; i < N; i++)
            v[i] += __shfl_xor_sync(0xffffffffu, v[i], o);
    if (lane == 0)
#pragma unroll
        for (int i = 0; i < N; i++) buf[wid * N + i] = v[i];
    __syncthreads();
#pragma unroll
    for (int i = 0; i < N; i++) {
        float s = 0.f;
#pragma unroll
        for (int w = 0; w < NW; w++) s += buf[w * N + i];
        v[i] = s;
    }
}

// ----------------------------------------------------------------------------
// hyp_p1: Gram pass 1 (VPT=8, 128 threads) -> 15 scalars per row
// ----------------------------------------------------------------------------
__global__ void __launch_bounds__(128) hyp_p1(
    const float* __restrict__ inp, const float* __restrict__ prevh,
    const float* __restrict__ bzp, const float* __restrict__ brp,
    const float* __restrict__ bhp)
{
    __shared__ float buf[4 * 19];
    const int tid = threadIdx.x;
    const size_t off = (size_t)blockIdx.x * NDIM;
    const int c = tid * 8;

    float s[19];
#pragma unroll
    for (int i = 0; i < 19; i++) s[i] = 0.f;

    float X[8], H[8], u[8], v[8], b[8];

    // x, H
    ld8f(inp + off + c, X);
    ld8f(prevh + off + c, H);
#pragma unroll
    for (int j = 0; j < 8; j++) {
        s[0] = fmaf(X[j], X[j], s[0]);
        s[1] = fmaf(H[j], H[j], s[1]);
    }
    // G0, G1, BZ
    ld8h(g_C + 0 * GSZ + off + c, u);
    ld8h(g_C + 1 * GSZ + off + c, v);
    ld8f(bzp + c, b);
#pragma unroll
    for (int j = 0; j < 8; j++) {
        s[2] = fmaf(u[j], u[j], s[2]);
        s[3] = fmaf(v[j], v[j], s[3]);
        s[4] = fmaf(u[j], v[j], s[4]);
        s[5] = fmaf(u[j], b[j], s[5]);
        s[6] = fmaf(v[j], b[j], s[6]);
        s[7] = fmaf(b[j], b[j], s[7]);
    }
    // G2, G3, BR
    ld8h(g_C + 2 * GSZ + off + c, u);
    ld8h(g_C + 3 * GSZ + off + c, v);
    ld8f(brp + c, b);
#pragma unroll
    for (int j = 0; j < 8; j++) {
        s[8]  = fmaf(u[j], u[j], s[8]);
        s[9]  = fmaf(v[j], v[j], s[9]);
        s[10] = fmaf(u[j], v[j], s[10]);
        s[11] = fmaf(u[j], b[j], s[11]);
        s[12] = fmaf(v[j], b[j], s[12]);
        s[13] = fmaf(b[j], b[j], s[13]);
    }
    // G5, BH
    ld8h(g_C + 5 * GSZ + off + c, u);
    ld8f(bhp + c, b);
#pragma unroll
    for (int j = 0; j < 8; j++) {
        s[14] = fmaf(u[j], u[j], s[14]);
        s[15] = fmaf(u[j], b[j], s[15]);
        s[16] = fmaf(b[j], b[j], s[16]);
    }
    // G4 (with H)
    ld8h(g_C + 4 * GSZ + off + c, u);
#pragma unroll
    for (int j = 0; j < 8; j++) {
        s[17] = fmaf(u[j], u[j], s[17]);
        s[18] = fmaf(u[j], H[j], s[18]);
    }

    blockReduceN<19, 4>(s, buf);
    if (tid >= 32) return;

    const float xx = s[0], hh = s[1];
    const float g00 = s[2], g11 = s[3], g01 = s[4], g0z = s[5], g1z = s[6], zz = s[7];
    const float g22 = s[8], g33 = s[9], g23 = s[10], g2r = s[11], g3r = s[12], rrb = s[13];
    const float g55 = s[14], g5h = s[15], bhbh = s[16], g44 = s[17], g4H = s[18];

    float inv_xn, xn, inv_hn, hn;
    safe_norm(xx, inv_xn, xn);
    safe_norm(hh, inv_hn, hn);
    const float atx = artanh_c(xn);
    const float ath = artanh_c(hn);

    const float t0 = mv_factor(g00, inv_xn, atx);
    const float t1 = mv_factor(g11, inv_hn, ath);
    const float t2 = mv_factor(g22, inv_xn, atx);
    const float t3 = mv_factor(g33, inv_hn, ath);
    const float t4 = mv_factor(g44, inv_xn, atx);
    const float t5 = mv_factor(g55, inv_hn, ath);

    float cA, cB;
    madd_coef(t1 * g1z, t1 * t1 * g11, zz, cA, cB);
    const float u1 = cA * t1, u2 = cB;
    madd_coef(t0 * (u1 * g01 + u2 * g0z), t0 * t0 * g00,
              u1 * u1 * g11 + 2.f * u1 * u2 * g1z + u2 * u2 * zz, cA, cB);
    const float w0 = cA * t0, w1 = cB * u1, w2 = cB * u2;
    const float nz2 = w0 * w0 * g00 + w1 * w1 * g11 + w2 * w2 * zz +
                      2.f * (w0 * w1 * g01 + w0 * w2 * g0z + w1 * w2 * g1z);
    float inv_nz, nz;
    safe_norm(nz2, inv_nz, nz);
    const float fz = artanh_c(nz) * inv_nz;

    madd_coef(t3 * g3r, t3 * t3 * g33, rrb, cA, cB);
    const float v1 = cA * t3, v2 = cB;
    madd_coef(t2 * (v1 * g23 + v2 * g2r), t2 * t2 * g22,
              v1 * v1 * g33 + 2.f * v1 * v2 * g3r + v2 * v2 * rrb, cA, cB);
    const float y0 = cA * t2, y1 = cB * v1, y2 = cB * v2;
    const float nr2 = y0 * y0 * g22 + y1 * y1 * g33 + y2 * y2 * rrb +
                      2.f * (y0 * y1 * g23 + y0 * y2 * g2r + y1 * y2 * g3r);
    float inv_nr, nr;
    safe_norm(nr2, inv_nr, nr);
    const float fr = artanh_c(nr) * inv_nr;

    madd_coef(t5 * g5h, t5 * t5 * g55, bhbh, cA, cB);
    const float d5 = cA * t5, db = cB;
    const float ahh2 = d5 * d5 * g55 + 2.f * d5 * db * g5h + db * db * bhbh;

    if (tid == 0) {
        float* S = g_S + blockIdx.x * 16;
        S[0] = w0;  S[1] = w1;  S[2] = w2;  S[3] = fz;
        S[4] = y0;  S[5] = y1;  S[6] = y2;  S[7] = fr;
        S[8] = d5;  S[9] = db;  S[10] = t4; S[11] = ahh2;
        S[12] = hh; S[13] = g44; S[14] = g4H;
    }
}

// ----------------------------------------------------------------------------
// hyp_p2: Gram pass 2 (VPT=8, 128 threads) -> output
// ----------------------------------------------------------------------------
__global__ void __launch_bounds__(128) hyp_p2(
    const float* __restrict__ prevh,
    const float* __restrict__ bzp, const float* __restrict__ brp,
    const float* __restrict__ bhp, float* __restrict__ out)
{
    __shared__ float buf[4 * 12];
    const int tid = threadIdx.x;
    const size_t off = (size_t)blockIdx.x * NDIM;
    const int c = tid * 8;
    const float* __restrict__ S = g_S + blockIdx.x * 16;

    const float w0 = S[0], w1 = S[1], w2 = S[2], fz = S[3];
    const float y0 = S[4], y1 = S[5], y2 = S[6], fr = S[7];
    const float d5 = S[8], db = S[9], t4 = S[10], ahh2 = S[11];
    const float hh = S[12], g44 = S[13], g4H = S[14];

    float z[8], q[8], H[8], G4[8];
    float ua[8], ub[8], bb[8];
    float s2[12];
#pragma unroll
    for (int i = 0; i < 12; i++) s2[i] = 0.f;

    // z
    ld8h(g_C + 0 * GSZ + off + c, ua);
    ld8h(g_C + 1 * GSZ + off + c, ub);
    ld8f(bzp + c, bb);
#pragma unroll
    for (int j = 0; j < 8; j++)
        z[j] = sigmoid_f(fz * (w0 * ua[j] + w1 * ub[j] + w2 * bb[j]));
    // r -> q
    ld8h(g_C + 2 * GSZ + off + c, ua);
    ld8h(g_C + 3 * GSZ + off + c, ub);
    ld8f(brp + c, bb);
#pragma unroll
    for (int j = 0; j < 8; j++)
        q[j] = sigmoid_f(fr * (y0 * ua[j] + y1 * ub[j] + y2 * bb[j]));
    ld8h(g_C + 5 * GSZ + off + c, ua);
    ld8f(bhp + c, bb);
#pragma unroll
    for (int j = 0; j < 8; j++)
        q[j] *= (d5 * ua[j] + db * bb[j]);

    ld8h(g_C + 4 * GSZ + off + c, G4);
    ld8f(prevh + off + c, H);

#pragma unroll
    for (int j = 0; j < 8; j++) {
        const float zh = z[j] * H[j], zq = z[j] * q[j], zg = z[j] * G4[j];
        s2[0]  = fmaf(q[j], q[j], s2[0]);
        s2[1]  = fmaf(q[j], G4[j], s2[1]);
        s2[2]  = fmaf(q[j], H[j], s2[2]);
        s2[3]  = fmaf(zh, zh, s2[3]);
        s2[4]  = fmaf(zh, zq, s2[4]);
        s2[5]  = fmaf(zh, zg, s2[5]);
        s2[6]  = fmaf(zq, zq, s2[6]);
        s2[7]  = fmaf(zq, zg, s2[7]);
        s2[8]  = fmaf(zg, zg, s2[8]);
        s2[9]  = fmaf(H[j], zh, s2[9]);
        s2[10] = fmaf(H[j], zq, s2[10]);
        s2[11] = fmaf(H[j], zg, s2[11]);
    }
    blockReduceN<12, 4>(s2, buf);
    const float qq = s2[0], qg4 = s2[1], qh = s2[2];
    const float s11 = s2[3], s12 = s2[4], s13 = s2[5];
    const float s22 = s2[6], s23 = s2[7], s33 = s2[8];
    const float hzh = s2[9], hzq = s2[10], hzg4 = s2[11];

    float cA, cB;
    float inv_na, na, inv_nq, nq;
    safe_norm(ahh2, inv_na, na);
    safe_norm(qq, inv_nq, nq);
    const float tp = tanh_pos(nq * inv_na * artanh_c(na)) * inv_nq;

    madd_coef(tp * t4 * qg4, tp * tp * qq, t4 * t4 * g44, cA, cB);
    const float bq = cA * tp, b4 = cB * t4;

    const float temp2 = bq * bq * qq + 2.f * bq * b4 * qg4 + b4 * b4 * g44;
    madd_coef(-(bq * qh + b4 * g4H), hh, temp2, cA, cB);
    const float alpha = -cA, bq2 = cB * bq, b42 = cB * b4;

    const float mh2 = alpha * alpha * hh + bq2 * bq2 * qq + b42 * b42 * g44 +
                      2.f * (alpha * bq2 * qh + alpha * b42 * g4H + bq2 * b42 * qg4);
    const float ux2 = alpha * alpha * s11 + bq2 * bq2 * s22 + b42 * b42 * s33 +
                      2.f * (alpha * bq2 * s12 + alpha * b42 * s13 + bq2 * b42 * s23);
    float inv_nmh, nmh, inv_nux, nux;
    safe_norm(mh2, inv_nmh, nmh);
    safe_norm(ux2, inv_nux, nux);
    const float tz = tanh_pos(nux * inv_nmh * artanh_c(nmh)) * inv_nux;

    madd_coef(tz * (alpha * hzh + bq2 * hzq + b42 * hzg4), hh, tz * tz * ux2,
              cA, cB);
    const float k0 = cA;
    const float kz = cB * tz;
    const float ka = kz * alpha, kb = kz * bq2, kc = kz * b42;

    float o[8];
#pragma unroll
    for (int j = 0; j < 8; j++)
        o[j] = k0 * H[j] + z[j] * (ka * H[j] + kb * q[j] + kc * G4[j]);
    *reinterpret_cast<float4*>(out + off + c) =
        make_float4(o[0], o[1], o[2], o[3]);
    *reinterpret_cast<float4*>(out + off + c + 4) =
        make_float4(o[4], o[5], o[6], o[7]);
}

// ----------------------------------------------------------------------------
// launch
// ----------------------------------------------------------------------------
extern "C" void kernel_launch(void* const* d_in, const int* in_sizes, int n_in,
                              void* d_out, int out_size)
{
    const float* inp   = (const float*)d_in[0];
    const float* prevh = (const float*)d_in[1];
    WPtrs wp;
    wp.w[0] = (const float*)d_in[2];  // w_inp_z
    wp.w[1] = (const float*)d_in[3];  // w_hid_z
    wp.w[2] = (const float*)d_in[5];  // w_inp_r
    wp.w[3] = (const float*)d_in[6];  // w_hid_r
    wp.w[4] = (const float*)d_in[8];  // w_inp_h
    wp.w[5] = (const float*)d_in[9];  // w_hid_h
    const float* b_z = (const float*)d_in[4];
    const float* b_r = (const float*)d_in[7];
    const float* b_h = (const float*)d_in[10];
    float* out = (float*)d_out;

    cudaFuncSetAttribute(gemm6, cudaFuncAttributeMaxDynamicSharedMemorySize,
                         SMEM_BYTES);

    split_act<<<8192, 256>>>(inp, prevh);
    split_wt<<<dim3(32, 32, 6), 256>>>(wp);
    gemm6<<<dim3(8, 32, 6), 256, SMEM_BYTES>>>();
    hyp_p1<<<MDIM, 128>>>(inp, prevh, b_z, b_r, b_h);
    hyp_p2<<<MDIM, 128>>>(prevh, b_z, b_r, b_h, out);
}